// round 1
// baseline (speedup 1.0000x reference)
#include <cuda_runtime.h>
#include <cuda_bf16.h>
#include <math.h>

// Problem dims (fixed)
#define BB 8
#define SS 1024
#define DD 2048
#define HH 16
#define HD 128
#define MTOK (BB * SS)          // 8192 tokens

// ---------------- scratch (device globals; allocation-free) ----------------
__device__ float g_Q[MTOK * DD];   // 64 MiB, pre-scaled by 1/sqrt(HD)
__device__ float g_K[MTOK * DD];
__device__ float g_V[MTOK * DD];
__device__ float g_C[MTOK * DD];   // attention context

// ---------------- tiled fp32 SGEMM: C[M,N] = scale * A[M,K] @ B[K,N] -------
// BM=BN=128, BK=8, 256 threads, 8x8 per thread split as 2x2 of 4-wide frags.
#define BM 128
#define BN 128
#define BK 8

__global__ __launch_bounds__(256) void sgemm_kernel(
    const float* __restrict__ A, const float* __restrict__ B,
    float* __restrict__ C, int M, int N, int K, float scale)
{
    __shared__ float As[BK][BM];
    __shared__ float Bs[BK][BN];

    const int t = threadIdx.x;
    const int tx = t & 15;      // col group
    const int ty = t >> 4;      // row group
    const int rowBase = blockIdx.y * BM;
    const int colBase = blockIdx.x * BN;

    // global->smem mapping
    const int aRow  = t >> 1;             // 0..127
    const int aCol4 = (t & 1) * 4;        // 0 or 4
    const int bRow  = t >> 5;             // 0..7
    const int bCol4 = (t & 31) * 4;       // 0..124

    const float* Aptr = A + (rowBase + aRow) * K;
    const float* Bptr = B + colBase;

    const int r0 = ty * 4, r1 = 64 + ty * 4;
    const int c0 = tx * 4, c1 = 64 + tx * 4;

    float acc[8][8];
#pragma unroll
    for (int i = 0; i < 8; i++)
#pragma unroll
        for (int j = 0; j < 8; j++) acc[i][j] = 0.f;

    for (int kt = 0; kt < K; kt += BK) {
        // load A tile (transposed store) and B tile
        float4 a4 = *(const float4*)(Aptr + kt + aCol4);
        As[aCol4 + 0][aRow] = a4.x;
        As[aCol4 + 1][aRow] = a4.y;
        As[aCol4 + 2][aRow] = a4.z;
        As[aCol4 + 3][aRow] = a4.w;
        *(float4*)&Bs[bRow][bCol4] =
            *(const float4*)(Bptr + (kt + bRow) * N + bCol4);
        __syncthreads();

#pragma unroll
        for (int k = 0; k < BK; k++) {
            float4 fa0 = *(float4*)&As[k][r0];
            float4 fa1 = *(float4*)&As[k][r1];
            float4 fb0 = *(float4*)&Bs[k][c0];
            float4 fb1 = *(float4*)&Bs[k][c1];
            float af[8] = {fa0.x, fa0.y, fa0.z, fa0.w, fa1.x, fa1.y, fa1.z, fa1.w};
            float bf[8] = {fb0.x, fb0.y, fb0.z, fb0.w, fb1.x, fb1.y, fb1.z, fb1.w};
#pragma unroll
            for (int i = 0; i < 8; i++)
#pragma unroll
                for (int j = 0; j < 8; j++)
                    acc[i][j] += af[i] * bf[j];
        }
        __syncthreads();
    }

    // epilogue
#pragma unroll
    for (int i = 0; i < 8; i++) {
        int r = rowBase + ((i < 4) ? (r0 + i) : (r1 + i - 4));
        float4 o0, o1;
        o0.x = acc[i][0] * scale; o0.y = acc[i][1] * scale;
        o0.z = acc[i][2] * scale; o0.w = acc[i][3] * scale;
        o1.x = acc[i][4] * scale; o1.y = acc[i][5] * scale;
        o1.z = acc[i][6] * scale; o1.w = acc[i][7] * scale;
        *(float4*)&C[r * N + colBase + c0] = o0;
        *(float4*)&C[r * N + colBase + c1] = o1;
    }
}

// ---------------- flash attention (fp32, online softmax) -------------------
// One CTA per (q-tile of 64, head, batch). 256 threads.
// smem: Qt d-major [128][64], KVt (K d-major [128][64] / V row-major [64][128]),
//       Ps [64][68], rowAlpha[64], rowL[64]  => 20864 floats = 83456 B dynamic.
#define ATT_SMEM_FLOATS (8192 + 8192 + 64 * 68 + 64 + 64)
#define ATT_SMEM_BYTES  (ATT_SMEM_FLOATS * 4)

__global__ __launch_bounds__(256) void attn_kernel(
    const float* __restrict__ Q, const float* __restrict__ K,
    const float* __restrict__ V, float* __restrict__ O)
{
    extern __shared__ float sm[];
    float* Qt     = sm;                    // [128][64]
    float* KVt    = sm + 8192;             // K: [128][64] or V: [64][128]
    float* Ps     = sm + 16384;            // [64][68]
    float* rAlpha = sm + 16384 + 64 * 68;  // [64]
    float* rL     = rAlpha + 64;           // [64]

    const int t  = threadIdx.x;
    const int tx = t & 15;
    const int ty = t >> 4;
    const int q0  = blockIdx.x * 64;
    const int hd0 = blockIdx.y * HD;
    const int tokBase = blockIdx.z * SS;

    // ---- load Q tile, d-major ----
    {
        const int tk = t & 63;
        const int dg = t >> 6;                   // 0..3  (32 d's each)
        const float* src = Q + (tokBase + q0 + tk) * DD + hd0 + dg * 32;
#pragma unroll
        for (int u = 0; u < 8; u++) {
            float4 v4 = *(const float4*)(src + u * 4);
            int d = dg * 32 + u * 4;
            Qt[(d + 0) * 64 + tk] = v4.x;
            Qt[(d + 1) * 64 + tk] = v4.y;
            Qt[(d + 2) * 64 + tk] = v4.z;
            Qt[(d + 3) * 64 + tk] = v4.w;
        }
    }

    float o_acc[4][8];
#pragma unroll
    for (int i = 0; i < 4; i++)
#pragma unroll
        for (int j = 0; j < 8; j++) o_acc[i][j] = 0.f;

    float my_m = -1e30f;   // used by threads t < 64 only
    float my_l = 0.f;

    for (int kt = 0; kt < SS / 64; kt++) {
        __syncthreads();   // KVt + Ps free for reuse (and Qt stored on first iter)

        // ---- load K tile, d-major ----
        {
            const int tk = t & 63;
            const int dg = t >> 6;
            const float* src = K + (tokBase + kt * 64 + tk) * DD + hd0 + dg * 32;
#pragma unroll
            for (int u = 0; u < 8; u++) {
                float4 v4 = *(const float4*)(src + u * 4);
                int d = dg * 32 + u * 4;
                KVt[(d + 0) * 64 + tk] = v4.x;
                KVt[(d + 1) * 64 + tk] = v4.y;
                KVt[(d + 2) * 64 + tk] = v4.z;
                KVt[(d + 3) * 64 + tk] = v4.w;
            }
        }
        __syncthreads();

        // ---- S = Q @ K^T : 64x64, reduce over d=128 ----
        float s[4][4];
#pragma unroll
        for (int i = 0; i < 4; i++)
#pragma unroll
            for (int j = 0; j < 4; j++) s[i][j] = 0.f;

        for (int d = 0; d < 128; d++) {
            float4 fa = *(float4*)&Qt[d * 64 + ty * 4];
            float4 fb = *(float4*)&KVt[d * 64 + tx * 4];
            float af[4] = {fa.x, fa.y, fa.z, fa.w};
            float bf[4] = {fb.x, fb.y, fb.z, fb.w};
#pragma unroll
            for (int i = 0; i < 4; i++)
#pragma unroll
                for (int j = 0; j < 4; j++)
                    s[i][j] += af[i] * bf[j];
        }
#pragma unroll
        for (int i = 0; i < 4; i++) {
            float4 w4 = make_float4(s[i][0], s[i][1], s[i][2], s[i][3]);
            *(float4*)&Ps[(ty * 4 + i) * 68 + tx * 4] = w4;
        }
        __syncthreads();

        // ---- load V tile (row-major) into KVt; K data no longer needed ----
        {
#pragma unroll
            for (int u = 0; u < 8; u++) {
                int lin = t + u * 256;           // float4 index, 0..2047
                int row = lin >> 5;
                int c4  = (lin & 31) * 4;
                *(float4*)&KVt[row * 128 + c4] =
                    *(const float4*)(V + (tokBase + kt * 64 + row) * DD + hd0 + c4);
            }
        }

        // ---- online softmax per q-row (threads 0..63) ----
        if (t < 64) {
            float tmax = -1e30f;
#pragma unroll 8
            for (int j = 0; j < 64; j++)
                tmax = fmaxf(tmax, Ps[t * 68 + j]);
            float m_new = fmaxf(my_m, tmax);
            float alpha = __expf(my_m - m_new);
            float sum = 0.f;
#pragma unroll 8
            for (int j = 0; j < 64; j++) {
                float p = __expf(Ps[t * 68 + j] - m_new);
                Ps[t * 68 + j] = p;
                sum += p;
            }
            my_l = my_l * alpha + sum;
            my_m = m_new;
            rAlpha[t] = alpha;
            rL[t] = my_l;
        }
        __syncthreads();

        // ---- rescale O, then O += P @ V ----
        float al[4];
#pragma unroll
        for (int i = 0; i < 4; i++) al[i] = rAlpha[ty * 4 + i];
#pragma unroll
        for (int i = 0; i < 4; i++)
#pragma unroll
            for (int j = 0; j < 8; j++) o_acc[i][j] *= al[i];

        for (int k = 0; k < 64; k++) {
            float a0 = Ps[(ty * 4 + 0) * 68 + k];
            float a1 = Ps[(ty * 4 + 1) * 68 + k];
            float a2 = Ps[(ty * 4 + 2) * 68 + k];
            float a3 = Ps[(ty * 4 + 3) * 68 + k];
            float4 fb0 = *(float4*)&KVt[k * 128 + tx * 4];
            float4 fb1 = *(float4*)&KVt[k * 128 + 64 + tx * 4];
            float bf[8] = {fb0.x, fb0.y, fb0.z, fb0.w, fb1.x, fb1.y, fb1.z, fb1.w};
            float av[4] = {a0, a1, a2, a3};
#pragma unroll
            for (int i = 0; i < 4; i++)
#pragma unroll
                for (int j = 0; j < 8; j++)
                    o_acc[i][j] += av[i] * bf[j];
        }
    }

    // ---- normalize and write context ----
    float li[4];
#pragma unroll
    for (int i = 0; i < 4; i++) li[i] = 1.f / rL[ty * 4 + i];
#pragma unroll
    for (int i = 0; i < 4; i++) {
        int row = tokBase + q0 + ty * 4 + i;
        float4 o0, o1;
        o0.x = o_acc[i][0] * li[i]; o0.y = o_acc[i][1] * li[i];
        o0.z = o_acc[i][2] * li[i]; o0.w = o_acc[i][3] * li[i];
        o1.x = o_acc[i][4] * li[i]; o1.y = o_acc[i][5] * li[i];
        o1.z = o_acc[i][6] * li[i]; o1.w = o_acc[i][7] * li[i];
        *(float4*)&O[row * DD + hd0 + tx * 4] = o0;
        *(float4*)&O[row * DD + hd0 + 64 + tx * 4] = o1;
    }
}

// ---------------- launch ----------------------------------------------------
extern "C" void kernel_launch(void* const* d_in, const int* in_sizes, int n_in,
                              void* d_out, int out_size)
{
    const float* inq  = (const float*)d_in[0];
    const float* inkv = (const float*)d_in[1];
    const float* Wq   = (const float*)d_in[2];
    const float* Wk   = (const float*)d_in[3];
    const float* Wv   = (const float*)d_in[4];
    const float* Wo   = (const float*)d_in[5];
    float* out = (float*)d_out;

    float *pQ, *pK, *pV, *pC;
    cudaGetSymbolAddress((void**)&pQ, g_Q);
    cudaGetSymbolAddress((void**)&pK, g_K);
    cudaGetSymbolAddress((void**)&pV, g_V);
    cudaGetSymbolAddress((void**)&pC, g_C);

    const float qscale = 1.0f / sqrtf((float)HD);

    dim3 gGrid(DD / BN, MTOK / BM);   // (16, 64)
    sgemm_kernel<<<gGrid, 256>>>(inq,  Wq, pQ, MTOK, DD, DD, qscale);
    sgemm_kernel<<<gGrid, 256>>>(inkv, Wk, pK, MTOK, DD, DD, 1.0f);
    sgemm_kernel<<<gGrid, 256>>>(inkv, Wv, pV, MTOK, DD, DD, 1.0f);

    cudaFuncSetAttribute(attn_kernel,
                         cudaFuncAttributeMaxDynamicSharedMemorySize,
                         ATT_SMEM_BYTES);
    dim3 aGrid(SS / 64, HH, BB);      // (16, 16, 8)
    attn_kernel<<<aGrid, 256, ATT_SMEM_BYTES>>>(pQ, pK, pV, pC);

    sgemm_kernel<<<gGrid, 256>>>(pC, Wo, out, MTOK, DD, DD, 1.0f);
}

// round 4
// speedup vs baseline: 1.8823x; 1.8823x over previous
#include <cuda_runtime.h>
#include <cuda_bf16.h>
#include <stdint.h>
#include <math.h>

// Problem dims (fixed)
#define BB 8
#define SS 1024
#define DD 2048
#define HH 16
#define HD 128
#define MTOK (BB * SS)     // 8192
#define BHN (BB * HH)      // 128 batch-heads

// ---------------- scratch (device globals; allocation-free) ----------------
__device__ float g_Q[(size_t)MTOK * DD];
__device__ float g_K[(size_t)MTOK * DD];
__device__ float g_V[(size_t)MTOK * DD];
__device__ float g_Vt[(size_t)MTOK * DD];      // per-batch transposed V
__device__ float g_C[(size_t)MTOK * DD];
__device__ float g_Wt[4][(size_t)DD * DD];     // transposed weights (N-major)
__device__ float g_S[(size_t)BHN * SS * SS];   // scores / probs (in-place softmax)

// ---------------- mma.sync GEMM (bf16 3-pass hi/lo split) -------------------
// D[M,N] = scale * A[M,K] @ B[N,K]^T   (A row-major, B row-major N-major)
// Block tile 128x128, BK=32, 256 threads (8 warps: 4m x 2n, 32x64 per warp).
// SMEM tile layout per operand: [row][128B] where bytes 0-63 = hi bf16 (32 k),
// bytes 64-127 = lo bf16, with SW128-style chunk swizzle (c ^= row&7).
#define GT 256
#define BKC 32
#define STAGE_BYTES 32768               // A tile 16KB + B tile 16KB
#define GEMM_SMEM (2 * STAGE_BYTES)     // 64 KB

__device__ __forceinline__ uint32_t smaddr(const void* p) {
    uint32_t a;
    asm("{ .reg .u64 t; cvta.to.shared.u64 t, %1; cvt.u32.u64 %0, t; }"
        : "=r"(a) : "l"(p));
    return a;
}
__device__ __forceinline__ void ldsm4(uint32_t addr, uint32_t* r) {
    asm volatile("ldmatrix.sync.aligned.m8n8.x4.shared.b16 {%0,%1,%2,%3}, [%4];"
                 : "=r"(r[0]), "=r"(r[1]), "=r"(r[2]), "=r"(r[3]) : "r"(addr));
}
__device__ __forceinline__ void mma16816(float* c, const uint32_t* a, const uint32_t* b) {
    asm volatile(
        "mma.sync.aligned.m16n8k16.row.col.f32.bf16.bf16.f32 "
        "{%0,%1,%2,%3},{%4,%5,%6,%7},{%8,%9},{%0,%1,%2,%3};"
        : "+f"(c[0]), "+f"(c[1]), "+f"(c[2]), "+f"(c[3])
        : "r"(a[0]), "r"(a[1]), "r"(a[2]), "r"(a[3]), "r"(b[0]), "r"(b[1]));
}

__device__ __forceinline__ void sts_split(char* tile, int row, int k4, float4 v) {
    __nv_bfloat16 hx = __float2bfloat16(v.x), hy = __float2bfloat16(v.y);
    __nv_bfloat16 hz = __float2bfloat16(v.z), hw = __float2bfloat16(v.w);
    __nv_bfloat162 h0, h1, l0, l1;
    h0.x = hx; h0.y = hy; h1.x = hz; h1.y = hw;
    l0.x = __float2bfloat16(v.x - __bfloat162float(hx));
    l0.y = __float2bfloat16(v.y - __bfloat162float(hy));
    l1.x = __float2bfloat16(v.z - __bfloat162float(hz));
    l1.y = __float2bfloat16(v.w - __bfloat162float(hw));
    const int c = k4 >> 1;
    const int h = (k4 & 1) * 8;
    const int sw = row & 7;
    uint2 hp, lp;
    hp.x = *(uint32_t*)&h0; hp.y = *(uint32_t*)&h1;
    lp.x = *(uint32_t*)&l0; lp.y = *(uint32_t*)&l1;
    *(uint2*)(tile + row * 128 + ((c ^ sw) << 4) + h) = hp;
    *(uint2*)(tile + row * 128 + (((c + 4) ^ sw) << 4) + h) = lp;
}

__global__ __launch_bounds__(GT) void gemm_mma(
    const float* __restrict__ A, long lda, long sAb, long sAh,
    const float* __restrict__ B, long ldb, long sBb, long sBh,
    float* __restrict__ C, long ldc, long sCb, long sCh,
    int K, int hdiv, float scale)
{
    extern __shared__ char sm[];

    const int t = threadIdx.x;
    const int lane = t & 31;
    const int wid = t >> 5;
    const int wm = wid >> 1;          // 0..3
    const int wn = wid & 1;           // 0..1
    const int zb = blockIdx.z / hdiv, zh = blockIdx.z % hdiv;

    const float* Ab = A + (size_t)zb * sAb + (size_t)zh * sAh
                        + (size_t)(blockIdx.y * 128) * lda;
    const float* Bb = B + (size_t)zb * sBb + (size_t)zh * sBh
                        + (size_t)(blockIdx.x * 128) * ldb;
    float* Cb = C + (size_t)zb * sCb + (size_t)zh * sCh
                  + (size_t)(blockIdx.y * 128) * ldc + (size_t)(blockIdx.x * 128);

    // ldmatrix lane decomposition
    const int sub = lane >> 3;        // 0..3 (which 8x8 matrix)
    const int rin = lane & 7;

    // global load mapping: k4 = float4 index within 32-float k-slab, rg = row group
    const int k4 = t & 7;
    const int rg = t >> 3;            // 0..31

    float acc[2][8][4];
#pragma unroll
    for (int i = 0; i < 2; i++)
#pragma unroll
        for (int j = 0; j < 8; j++)
#pragma unroll
            for (int q = 0; q < 4; q++) acc[i][j][q] = 0.f;

    const int NC = K / BKC;
    float4 ra[4], rb[4];

    // prologue: load + store chunk 0 into stage 0
#pragma unroll
    for (int u = 0; u < 4; u++) {
        ra[u] = *(const float4*)(Ab + (size_t)(rg + u * 32) * lda + k4 * 4);
        rb[u] = *(const float4*)(Bb + (size_t)(rg + u * 32) * ldb + k4 * 4);
    }
    {
        char* As = sm;
        char* Bs = sm + 16384;
#pragma unroll
        for (int u = 0; u < 4; u++) {
            sts_split(As, rg + u * 32, k4, ra[u]);
            sts_split(Bs, rg + u * 32, k4, rb[u]);
        }
    }

    for (int c = 0; c < NC; c++) {
        if (c + 1 < NC) {
            const int kt = (c + 1) * BKC;
#pragma unroll
            for (int u = 0; u < 4; u++) {
                ra[u] = *(const float4*)(Ab + (size_t)(rg + u * 32) * lda + kt + k4 * 4);
                rb[u] = *(const float4*)(Bb + (size_t)(rg + u * 32) * ldb + kt + k4 * 4);
            }
        }
        __syncthreads();

        char* As = sm + (c & 1) * STAGE_BYTES;
        char* Bs = As + 16384;
        const uint32_t sA = smaddr(As);
        const uint32_t sB = smaddr(Bs);

#pragma unroll
        for (int ks = 0; ks < 2; ks++) {
            uint32_t Ah[2][4], Al[2][4], Bh[4][4], Bl[4][4];
#pragma unroll
            for (int i = 0; i < 2; i++) {
                int arow = wm * 32 + i * 16 + rin + (sub & 1) * 8;
                int swz = arow & 7;
                int ch = 2 * ks + (sub >> 1);
                int cl = ch + 4;
                ldsm4(sA + arow * 128 + ((ch ^ swz) << 4), Ah[i]);
                ldsm4(sA + arow * 128 + ((cl ^ swz) << 4), Al[i]);
            }
#pragma unroll
            for (int p = 0; p < 4; p++) {
                int brow = wn * 64 + p * 16 + rin + (sub >> 1) * 8;
                int swz = brow & 7;
                int ch = 2 * ks + (sub & 1);
                int cl = ch + 4;
                ldsm4(sB + brow * 128 + ((ch ^ swz) << 4), Bh[p]);
                ldsm4(sB + brow * 128 + ((cl ^ swz) << 4), Bl[p]);
            }
#pragma unroll
            for (int i = 0; i < 2; i++)
#pragma unroll
                for (int p = 0; p < 4; p++) {
                    mma16816(acc[i][2 * p + 0], Ah[i], &Bh[p][0]);   // hi*hi
                    mma16816(acc[i][2 * p + 1], Ah[i], &Bh[p][2]);
                    mma16816(acc[i][2 * p + 0], Ah[i], &Bl[p][0]);   // hi*lo
                    mma16816(acc[i][2 * p + 1], Ah[i], &Bl[p][2]);
                    mma16816(acc[i][2 * p + 0], Al[i], &Bh[p][0]);   // lo*hi
                    mma16816(acc[i][2 * p + 1], Al[i], &Bh[p][2]);
                }
        }

        if (c + 1 < NC) {
            char* An = sm + ((c + 1) & 1) * STAGE_BYTES;
            char* Bn = An + 16384;
#pragma unroll
            for (int u = 0; u < 4; u++) {
                sts_split(An, rg + u * 32, k4, ra[u]);
                sts_split(Bn, rg + u * 32, k4, rb[u]);
            }
        }
    }

    // epilogue: direct STG (32B-sector friendly float2 stores)
#pragma unroll
    for (int i = 0; i < 2; i++) {
        int r = wm * 32 + i * 16 + (lane >> 2);
#pragma unroll
        for (int j = 0; j < 8; j++) {
            int cc = wn * 64 + j * 8 + (lane & 3) * 2;
            float2 v0, v1;
            v0.x = acc[i][j][0] * scale; v0.y = acc[i][j][1] * scale;
            v1.x = acc[i][j][2] * scale; v1.y = acc[i][j][3] * scale;
            *(float2*)&Cb[(size_t)r * ldc + cc] = v0;
            *(float2*)&Cb[(size_t)(r + 8) * ldc + cc] = v1;
        }
    }
}

// ---------------- fp32 transpose: out[z][C][R] = in[z][R][C] ---------------
__global__ __launch_bounds__(256) void transpose_k(
    const float* __restrict__ in, float* __restrict__ out, int R, int C)
{
    __shared__ float tile[32][33];
    size_t zo = (size_t)blockIdx.z * R * C;
    int x = blockIdx.x * 32 + threadIdx.x;
    int y0 = blockIdx.y * 32;
#pragma unroll
    for (int i = threadIdx.y; i < 32; i += 8)
        tile[i][threadIdx.x] = in[zo + (size_t)(y0 + i) * C + x];
    __syncthreads();
    int xo = blockIdx.y * 32 + threadIdx.x;
    int yo0 = blockIdx.x * 32;
#pragma unroll
    for (int i = threadIdx.y; i < 32; i += 8)
        out[zo + (size_t)(yo0 + i) * R + xo] = tile[threadIdx.x][i];
}

// ---------------- in-place row softmax (rows of 1024) ----------------------
__global__ __launch_bounds__(256) void softmax_k(float* __restrict__ S)
{
    __shared__ float redm[8];
    __shared__ float reds[8];
    float* p = S + (size_t)blockIdx.x * SS;
    const int t = threadIdx.x;

    float4 v = *(float4*)(p + t * 4);
    float m = fmaxf(fmaxf(v.x, v.y), fmaxf(v.z, v.w));
#pragma unroll
    for (int o = 16; o; o >>= 1) m = fmaxf(m, __shfl_xor_sync(~0u, m, o));
    if ((t & 31) == 0) redm[t >> 5] = m;
    __syncthreads();
    float M = redm[0];
#pragma unroll
    for (int i = 1; i < 8; i++) M = fmaxf(M, redm[i]);

    float4 e;
    e.x = __expf(v.x - M); e.y = __expf(v.y - M);
    e.z = __expf(v.z - M); e.w = __expf(v.w - M);
    float s = e.x + e.y + e.z + e.w;
#pragma unroll
    for (int o = 16; o; o >>= 1) s += __shfl_xor_sync(~0u, s, o);
    if ((t & 31) == 0) reds[t >> 5] = s;
    __syncthreads();
    float Sum = 0.f;
#pragma unroll
    for (int i = 0; i < 8; i++) Sum += reds[i];
    float inv = 1.0f / Sum;

    e.x *= inv; e.y *= inv; e.z *= inv; e.w *= inv;
    *(float4*)(p + t * 4) = e;
}

// ---------------- launch ----------------------------------------------------
extern "C" void kernel_launch(void* const* d_in, const int* in_sizes, int n_in,
                              void* d_out, int out_size)
{
    const float* inq  = (const float*)d_in[0];
    const float* inkv = (const float*)d_in[1];
    const float* Wq   = (const float*)d_in[2];
    const float* Wk   = (const float*)d_in[3];
    const float* Wv   = (const float*)d_in[4];
    const float* Wo   = (const float*)d_in[5];
    float* out = (float*)d_out;

    float *pQ, *pK, *pV, *pVt, *pC, *pWt, *pS;
    cudaGetSymbolAddress((void**)&pQ,  g_Q);
    cudaGetSymbolAddress((void**)&pK,  g_K);
    cudaGetSymbolAddress((void**)&pV,  g_V);
    cudaGetSymbolAddress((void**)&pVt, g_Vt);
    cudaGetSymbolAddress((void**)&pC,  g_C);
    cudaGetSymbolAddress((void**)&pWt, g_Wt);
    cudaGetSymbolAddress((void**)&pS,  g_S);
    float* pWtq = pWt;
    float* pWtk = pWt + (size_t)DD * DD;
    float* pWtv = pWt + (size_t)2 * DD * DD;
    float* pWto = pWt + (size_t)3 * DD * DD;

    cudaFuncSetAttribute(gemm_mma, cudaFuncAttributeMaxDynamicSharedMemorySize, GEMM_SMEM);

    const float qscale = 1.0f / sqrtf((float)HD);
    dim3 tb(32, 8);

    // transpose weights to [N][K]
    transpose_k<<<dim3(DD / 32, DD / 32, 1), tb>>>(Wq, pWtq, DD, DD);
    transpose_k<<<dim3(DD / 32, DD / 32, 1), tb>>>(Wk, pWtk, DD, DD);
    transpose_k<<<dim3(DD / 32, DD / 32, 1), tb>>>(Wv, pWtv, DD, DD);
    transpose_k<<<dim3(DD / 32, DD / 32, 1), tb>>>(Wo, pWto, DD, DD);

    // projections
    dim3 pg(DD / 128, MTOK / 128, 1);   // (16, 64)
    gemm_mma<<<pg, GT, GEMM_SMEM>>>(inq,  DD, 0, 0, pWtq, DD, 0, 0, pQ, DD, 0, 0, DD, 1, qscale);
    gemm_mma<<<pg, GT, GEMM_SMEM>>>(inkv, DD, 0, 0, pWtk, DD, 0, 0, pK, DD, 0, 0, DD, 1, 1.0f);
    gemm_mma<<<pg, GT, GEMM_SMEM>>>(inkv, DD, 0, 0, pWtv, DD, 0, 0, pV, DD, 0, 0, DD, 1, 1.0f);

    // per-batch V transpose: [b][1024][2048] -> [b][2048][1024]
    transpose_k<<<dim3(DD / 32, SS / 32, BB), tb>>>(pV, pVt, SS, DD);

    // scores: S[b,h][q][k] = Q . K^T over d (K=128)
    dim3 sg(SS / 128, SS / 128, BHN);   // (8, 8, 128)
    gemm_mma<<<sg, GT, GEMM_SMEM>>>(
        pQ, DD, (long)SS * DD, HD,
        pK, DD, (long)SS * DD, HD,
        pS, SS, (long)HH * SS * SS, (long)SS * SS,
        HD, HH, 1.0f);

    // softmax in place
    softmax_k<<<(unsigned)((size_t)BHN * SS), 256>>>(pS);

    // ctx: C[b][q][h*128+d] = P . Vt^T over k (K=1024)
    dim3 cg(HD / 128, SS / 128, BHN);   // (1, 8, 128)
    gemm_mma<<<cg, GT, GEMM_SMEM>>>(
        pS, SS, (long)HH * SS * SS, (long)SS * SS,
        pVt, SS, (long)DD * SS, (long)HD * SS,
        pC, DD, (long)SS * DD, HD,
        SS, HH, 1.0f);

    // output projection
    gemm_mma<<<pg, GT, GEMM_SMEM>>>(pC, DD, 0, 0, pWto, DD, 0, 0, out, DD, 0, 0, DD, 1, 1.0f);
}

// round 5
// speedup vs baseline: 2.9546x; 1.5697x over previous
#include <cuda_runtime.h>
#include <cuda_fp16.h>
#include <stdint.h>
#include <math.h>

// Problem dims (fixed)
#define BB 8
#define SS 1024
#define DD 2048
#define HH 16
#define HD 128
#define MTOK (BB * SS)     // 8192
#define BHN (BB * HH)      // 128 batch-heads

// ---------------- scratch (device globals; allocation-free) ----------------
__device__ float g_Q[(size_t)MTOK * DD];
__device__ float g_K[(size_t)MTOK * DD];
__device__ float g_V[(size_t)MTOK * DD];
__device__ float g_Vt[(size_t)MTOK * DD];      // per-batch transposed V
__device__ float g_C[(size_t)MTOK * DD];
__device__ float g_Wt[4][(size_t)DD * DD];     // transposed weights (N-major)
__device__ float g_S[(size_t)BHN * SS * SS];   // scores / probs (in-place softmax)

// ---------------- mma.sync GEMM (fp16 2-pass: A hi/lo split, B single) ------
// D[M,N] = scale * A[M,K] @ B[N,K]^T   (A row-major, B row-major N-major)
// Block tile 128x128, BK=32, 256 threads (8 warps: 4m x 2n, 32x64 per warp).
// SMEM per-operand tile: [row][128B]; bytes 0-63 = hi fp16 (32 k-values),
// bytes 64-127 = lo fp16 (A only; B region unused), chunk swizzle c ^= row&7.
#define GT 256
#define BKC 32
#define STAGE_BYTES 32768               // A tile 16KB + B tile 16KB
#define GEMM_SMEM (2 * STAGE_BYTES)     // 64 KB

__device__ __forceinline__ uint32_t smaddr(const void* p) {
    uint32_t a;
    asm("{ .reg .u64 t; cvta.to.shared.u64 t, %1; cvt.u32.u64 %0, t; }"
        : "=r"(a) : "l"(p));
    return a;
}
__device__ __forceinline__ void ldsm4(uint32_t addr, uint32_t* r) {
    asm volatile("ldmatrix.sync.aligned.m8n8.x4.shared.b16 {%0,%1,%2,%3}, [%4];"
                 : "=r"(r[0]), "=r"(r[1]), "=r"(r[2]), "=r"(r[3]) : "r"(addr));
}
__device__ __forceinline__ void mma16816(float* c, const uint32_t* a, const uint32_t* b) {
    asm volatile(
        "mma.sync.aligned.m16n8k16.row.col.f32.f16.f16.f32 "
        "{%0,%1,%2,%3},{%4,%5,%6,%7},{%8,%9},{%0,%1,%2,%3};"
        : "+f"(c[0]), "+f"(c[1]), "+f"(c[2]), "+f"(c[3])
        : "r"(a[0]), "r"(a[1]), "r"(a[2]), "r"(a[3]), "r"(b[0]), "r"(b[1]));
}

// A: store fp16 hi chunk + fp16 lo (residual) chunk
__device__ __forceinline__ void sts_split(char* tile, int row, int k4, float4 v) {
    __half hx = __float2half_rn(v.x), hy = __float2half_rn(v.y);
    __half hz = __float2half_rn(v.z), hw = __float2half_rn(v.w);
    __half2 h0, h1, l0, l1;
    h0.x = hx; h0.y = hy; h1.x = hz; h1.y = hw;
    l0.x = __float2half_rn(v.x - __half2float(hx));
    l0.y = __float2half_rn(v.y - __half2float(hy));
    l1.x = __float2half_rn(v.z - __half2float(hz));
    l1.y = __float2half_rn(v.w - __half2float(hw));
    const int c = k4 >> 1;
    const int h = (k4 & 1) * 8;
    const int sw = row & 7;
    uint2 hp, lp;
    hp.x = *(uint32_t*)&h0; hp.y = *(uint32_t*)&h1;
    lp.x = *(uint32_t*)&l0; lp.y = *(uint32_t*)&l1;
    *(uint2*)(tile + row * 128 + ((c ^ sw) << 4) + h) = hp;
    *(uint2*)(tile + row * 128 + (((c + 4) ^ sw) << 4) + h) = lp;
}

// B: store fp16 hi chunk only
__device__ __forceinline__ void sts_hi(char* tile, int row, int k4, float4 v) {
    __half2 h0, h1;
    h0.x = __float2half_rn(v.x); h0.y = __float2half_rn(v.y);
    h1.x = __float2half_rn(v.z); h1.y = __float2half_rn(v.w);
    const int c = k4 >> 1;
    const int h = (k4 & 1) * 8;
    const int sw = row & 7;
    uint2 hp;
    hp.x = *(uint32_t*)&h0; hp.y = *(uint32_t*)&h1;
    *(uint2*)(tile + row * 128 + ((c ^ sw) << 4) + h) = hp;
}

__global__ __launch_bounds__(GT) void gemm_mma(
    const float* __restrict__ A, long lda, long sAb, long sAh,
    const float* __restrict__ B, long ldb, long sBb, long sBh,
    float* __restrict__ C, long ldc, long sCb, long sCh,
    int K, int hdiv, float scale)
{
    extern __shared__ char sm[];

    const int t = threadIdx.x;
    const int lane = t & 31;
    const int wid = t >> 5;
    const int wm = wid >> 1;          // 0..3
    const int wn = wid & 1;           // 0..1
    const int zb = blockIdx.z / hdiv, zh = blockIdx.z % hdiv;

    const float* Ab = A + (size_t)zb * sAb + (size_t)zh * sAh
                        + (size_t)(blockIdx.y * 128) * lda;
    const float* Bb = B + (size_t)zb * sBb + (size_t)zh * sBh
                        + (size_t)(blockIdx.x * 128) * ldb;
    float* Cb = C + (size_t)zb * sCb + (size_t)zh * sCh
                  + (size_t)(blockIdx.y * 128) * ldc + (size_t)(blockIdx.x * 128);

    const int sub = lane >> 3;        // 0..3 (which 8x8 matrix)
    const int rin = lane & 7;

    const int k4 = t & 7;             // float4 index within 32-float k-slab
    const int rg = t >> 3;            // row group 0..31

    float acc[2][8][4];
#pragma unroll
    for (int i = 0; i < 2; i++)
#pragma unroll
        for (int j = 0; j < 8; j++)
#pragma unroll
            for (int q = 0; q < 4; q++) acc[i][j][q] = 0.f;

    const int NC = K / BKC;
    float4 ra[4], rb[4];

    // prologue: load + store chunk 0 into stage 0
#pragma unroll
    for (int u = 0; u < 4; u++) {
        ra[u] = *(const float4*)(Ab + (size_t)(rg + u * 32) * lda + k4 * 4);
        rb[u] = *(const float4*)(Bb + (size_t)(rg + u * 32) * ldb + k4 * 4);
    }
    {
        char* As = sm;
        char* Bs = sm + 16384;
#pragma unroll
        for (int u = 0; u < 4; u++) {
            sts_split(As, rg + u * 32, k4, ra[u]);
            sts_hi(Bs, rg + u * 32, k4, rb[u]);
        }
    }

    for (int c = 0; c < NC; c++) {
        if (c + 1 < NC) {
            const int kt = (c + 1) * BKC;
#pragma unroll
            for (int u = 0; u < 4; u++) {
                ra[u] = *(const float4*)(Ab + (size_t)(rg + u * 32) * lda + kt + k4 * 4);
                rb[u] = *(const float4*)(Bb + (size_t)(rg + u * 32) * ldb + kt + k4 * 4);
            }
        }
        __syncthreads();

        char* As = sm + (c & 1) * STAGE_BYTES;
        char* Bs = As + 16384;
        const uint32_t sA = smaddr(As);
        const uint32_t sB = smaddr(Bs);

#pragma unroll
        for (int ks = 0; ks < 2; ks++) {
            uint32_t Ah[2][4], Al[2][4], Bh[4][4];
#pragma unroll
            for (int i = 0; i < 2; i++) {
                int arow = wm * 32 + i * 16 + rin + (sub & 1) * 8;
                int swz = arow & 7;
                int ch = 2 * ks + (sub >> 1);
                int cl = ch + 4;
                ldsm4(sA + arow * 128 + ((ch ^ swz) << 4), Ah[i]);
                ldsm4(sA + arow * 128 + ((cl ^ swz) << 4), Al[i]);
            }
#pragma unroll
            for (int p = 0; p < 4; p++) {
                int brow = wn * 64 + p * 16 + rin + (sub >> 1) * 8;
                int swz = brow & 7;
                int ch = 2 * ks + (sub & 1);
                ldsm4(sB + brow * 128 + ((ch ^ swz) << 4), Bh[p]);
            }
#pragma unroll
            for (int i = 0; i < 2; i++)
#pragma unroll
                for (int p = 0; p < 4; p++) {
                    mma16816(acc[i][2 * p + 0], Ah[i], &Bh[p][0]);   // hi*B
                    mma16816(acc[i][2 * p + 1], Ah[i], &Bh[p][2]);
                    mma16816(acc[i][2 * p + 0], Al[i], &Bh[p][0]);   // lo*B
                    mma16816(acc[i][2 * p + 1], Al[i], &Bh[p][2]);
                }
        }

        if (c + 1 < NC) {
            char* An = sm + ((c + 1) & 1) * STAGE_BYTES;
            char* Bn = An + 16384;
#pragma unroll
            for (int u = 0; u < 4; u++) {
                sts_split(An, rg + u * 32, k4, ra[u]);
                sts_hi(Bn, rg + u * 32, k4, rb[u]);
            }
        }
    }

    // epilogue: direct STG (32B-sector friendly float2 stores)
#pragma unroll
    for (int i = 0; i < 2; i++) {
        int r = wm * 32 + i * 16 + (lane >> 2);
#pragma unroll
        for (int j = 0; j < 8; j++) {
            int cc = wn * 64 + j * 8 + (lane & 3) * 2;
            float2 v0, v1;
            v0.x = acc[i][j][0] * scale; v0.y = acc[i][j][1] * scale;
            v1.x = acc[i][j][2] * scale; v1.y = acc[i][j][3] * scale;
            *(float2*)&Cb[(size_t)r * ldc + cc] = v0;
            *(float2*)&Cb[(size_t)(r + 8) * ldc + cc] = v1;
        }
    }
}

// ---------------- fp32 transpose: out[z][C][R] = in[z][R][C] ---------------
__global__ __launch_bounds__(256) void transpose_k(
    const float* __restrict__ in, float* __restrict__ out, int R, int C)
{
    __shared__ float tile[32][33];
    size_t zo = (size_t)blockIdx.z * R * C;
    int x = blockIdx.x * 32 + threadIdx.x;
    int y0 = blockIdx.y * 32;
#pragma unroll
    for (int i = threadIdx.y; i < 32; i += 8)
        tile[i][threadIdx.x] = in[zo + (size_t)(y0 + i) * C + x];
    __syncthreads();
    int xo = blockIdx.y * 32 + threadIdx.x;
    int yo0 = blockIdx.x * 32;
#pragma unroll
    for (int i = threadIdx.y; i < 32; i += 8)
        out[zo + (size_t)(yo0 + i) * R + xo] = tile[threadIdx.x][i];
}

// ---------------- in-place row softmax (rows of 1024) ----------------------
__global__ __launch_bounds__(256) void softmax_k(float* __restrict__ S)
{
    __shared__ float redm[8];
    __shared__ float reds[8];
    float* p = S + (size_t)blockIdx.x * SS;
    const int t = threadIdx.x;

    float4 v = *(float4*)(p + t * 4);
    float m = fmaxf(fmaxf(v.x, v.y), fmaxf(v.z, v.w));
#pragma unroll
    for (int o = 16; o; o >>= 1) m = fmaxf(m, __shfl_xor_sync(~0u, m, o));
    if ((t & 31) == 0) redm[t >> 5] = m;
    __syncthreads();
    float M = redm[0];
#pragma unroll
    for (int i = 1; i < 8; i++) M = fmaxf(M, redm[i]);

    float4 e;
    e.x = __expf(v.x - M); e.y = __expf(v.y - M);
    e.z = __expf(v.z - M); e.w = __expf(v.w - M);
    float s = e.x + e.y + e.z + e.w;
#pragma unroll
    for (int o = 16; o; o >>= 1) s += __shfl_xor_sync(~0u, s, o);
    if ((t & 31) == 0) reds[t >> 5] = s;
    __syncthreads();
    float Sum = 0.f;
#pragma unroll
    for (int i = 0; i < 8; i++) Sum += reds[i];
    float inv = 1.0f / Sum;

    e.x *= inv; e.y *= inv; e.z *= inv; e.w *= inv;
    *(float4*)(p + t * 4) = e;
}

// ---------------- launch ----------------------------------------------------
extern "C" void kernel_launch(void* const* d_in, const int* in_sizes, int n_in,
                              void* d_out, int out_size)
{
    const float* inq  = (const float*)d_in[0];
    const float* inkv = (const float*)d_in[1];
    const float* Wq   = (const float*)d_in[2];
    const float* Wk   = (const float*)d_in[3];
    const float* Wv   = (const float*)d_in[4];
    const float* Wo   = (const float*)d_in[5];
    float* out = (float*)d_out;

    float *pQ, *pK, *pV, *pVt, *pC, *pWt, *pS;
    cudaGetSymbolAddress((void**)&pQ,  g_Q);
    cudaGetSymbolAddress((void**)&pK,  g_K);
    cudaGetSymbolAddress((void**)&pV,  g_V);
    cudaGetSymbolAddress((void**)&pVt, g_Vt);
    cudaGetSymbolAddress((void**)&pC,  g_C);
    cudaGetSymbolAddress((void**)&pWt, g_Wt);
    cudaGetSymbolAddress((void**)&pS,  g_S);
    float* pWtq = pWt;
    float* pWtk = pWt + (size_t)DD * DD;
    float* pWtv = pWt + (size_t)2 * DD * DD;
    float* pWto = pWt + (size_t)3 * DD * DD;

    cudaFuncSetAttribute(gemm_mma, cudaFuncAttributeMaxDynamicSharedMemorySize, GEMM_SMEM);

    const float qscale = 1.0f / sqrtf((float)HD);
    dim3 tb(32, 8);

    // transpose weights to [N][K]
    transpose_k<<<dim3(DD / 32, DD / 32, 1), tb>>>(Wq, pWtq, DD, DD);
    transpose_k<<<dim3(DD / 32, DD / 32, 1), tb>>>(Wk, pWtk, DD, DD);
    transpose_k<<<dim3(DD / 32, DD / 32, 1), tb>>>(Wv, pWtv, DD, DD);
    transpose_k<<<dim3(DD / 32, DD / 32, 1), tb>>>(Wo, pWto, DD, DD);

    // projections
    dim3 pg(DD / 128, MTOK / 128, 1);   // (16, 64)
    gemm_mma<<<pg, GT, GEMM_SMEM>>>(inq,  DD, 0, 0, pWtq, DD, 0, 0, pQ, DD, 0, 0, DD, 1, qscale);
    gemm_mma<<<pg, GT, GEMM_SMEM>>>(inkv, DD, 0, 0, pWtk, DD, 0, 0, pK, DD, 0, 0, DD, 1, 1.0f);
    gemm_mma<<<pg, GT, GEMM_SMEM>>>(inkv, DD, 0, 0, pWtv, DD, 0, 0, pV, DD, 0, 0, DD, 1, 1.0f);

    // per-batch V transpose: [b][1024][2048] -> [b][2048][1024]
    transpose_k<<<dim3(DD / 32, SS / 32, BB), tb>>>(pV, pVt, SS, DD);

    // scores: S[b,h][q][k] = Q . K^T over d (K=128)
    dim3 sg(SS / 128, SS / 128, BHN);   // (8, 8, 128)
    gemm_mma<<<sg, GT, GEMM_SMEM>>>(
        pQ, DD, (long)SS * DD, HD,
        pK, DD, (long)SS * DD, HD,
        pS, SS, (long)HH * SS * SS, (long)SS * SS,
        HD, HH, 1.0f);

    // softmax in place
    softmax_k<<<(unsigned)((size_t)BHN * SS), 256>>>(pS);

    // ctx: C[b][q][h*128+d] = P . Vt^T over k (K=1024)
    dim3 cg(HD / 128, SS / 128, BHN);   // (1, 8, 128)
    gemm_mma<<<cg, GT, GEMM_SMEM>>>(
        pS, SS, (long)HH * SS * SS, (long)SS * SS,
        pVt, SS, (long)DD * SS, (long)HD * SS,
        pC, DD, (long)SS * DD, HD,
        SS, HH, 1.0f);

    // output projection
    gemm_mma<<<pg, GT, GEMM_SMEM>>>(pC, DD, 0, 0, pWto, DD, 0, 0, out, DD, 0, 0, DD, 1, 1.0f);
}

// round 6
// speedup vs baseline: 2.9690x; 1.0049x over previous
#include <cuda_runtime.h>
#include <cuda_fp16.h>
#include <stdint.h>
#include <math.h>

// Problem dims (fixed)
#define BB 8
#define SS 1024
#define DD 2048
#define HH 16
#define HD 128
#define MTOK (BB * SS)     // 8192
#define BHN (BB * HH)      // 128 batch-heads

// ---------------- scratch (device globals; allocation-free) ----------------
__device__ float g_Q[(size_t)MTOK * DD];
__device__ float g_K[(size_t)MTOK * DD];
__device__ float g_V[(size_t)MTOK * DD];
__device__ float g_Vt[(size_t)MTOK * DD];      // per-batch transposed V
__device__ float g_C[(size_t)MTOK * DD];
__device__ float g_Wt[4][(size_t)DD * DD];     // transposed weights (N-major)
__device__ float g_S[(size_t)BHN * SS * SS];   // scores (fp32)
__device__ __half g_P[(size_t)BHN * SS * SS];  // probs (fp16, softmax output)

// ---------------- mma.sync GEMM -------------------------------------------
// D[M,N] = scale * A[M,K] @ B[N,K]^T
// MODE 0: A fp32, hi/lo split, 2-pass (projections)
// MODE 1: A fp32, rounded to fp16, 1-pass (scores)
// MODE 2: A fp16 direct, 1-pass (ctx: A = P)
// B always fp32 -> fp16 rounded.
// Block tile 128x128, BK=32, 256 threads (8 warps: 4m x 2n, 32x64 per warp).
// SMEM per-operand tile: [row][128B]; logical chunks c=0..3 hold hi fp16
// (32 k-values), c=4..7 hold lo fp16 (MODE 0 A only); swizzle (c ^ (row&7)).
#define GT 256
#define BKC 32
#define STAGE_BYTES 32768               // A tile 16KB + B tile 16KB
#define GEMM_SMEM (2 * STAGE_BYTES)     // 64 KB

__device__ __forceinline__ uint32_t smaddr(const void* p) {
    uint32_t a;
    asm("{ .reg .u64 t; cvta.to.shared.u64 t, %1; cvt.u32.u64 %0, t; }"
        : "=r"(a) : "l"(p));
    return a;
}
__device__ __forceinline__ void ldsm4(uint32_t addr, uint32_t* r) {
    asm volatile("ldmatrix.sync.aligned.m8n8.x4.shared.b16 {%0,%1,%2,%3}, [%4];"
                 : "=r"(r[0]), "=r"(r[1]), "=r"(r[2]), "=r"(r[3]) : "r"(addr));
}
__device__ __forceinline__ void mma16816(float* c, const uint32_t* a, const uint32_t* b) {
    asm volatile(
        "mma.sync.aligned.m16n8k16.row.col.f32.f16.f16.f32 "
        "{%0,%1,%2,%3},{%4,%5,%6,%7},{%8,%9},{%0,%1,%2,%3};"
        : "+f"(c[0]), "+f"(c[1]), "+f"(c[2]), "+f"(c[3])
        : "r"(a[0]), "r"(a[1]), "r"(a[2]), "r"(a[3]), "r"(b[0]), "r"(b[1]));
}

// fp32 -> fp16 hi + fp16 lo residual (MODE 0 A)
__device__ __forceinline__ void sts_split(char* tile, int row, int k4, float4 v) {
    __half hx = __float2half_rn(v.x), hy = __float2half_rn(v.y);
    __half hz = __float2half_rn(v.z), hw = __float2half_rn(v.w);
    __half2 h0, h1, l0, l1;
    h0.x = hx; h0.y = hy; h1.x = hz; h1.y = hw;
    l0.x = __float2half_rn(v.x - __half2float(hx));
    l0.y = __float2half_rn(v.y - __half2float(hy));
    l1.x = __float2half_rn(v.z - __half2float(hz));
    l1.y = __float2half_rn(v.w - __half2float(hw));
    const int c = k4 >> 1;
    const int h = (k4 & 1) * 8;
    const int sw = row & 7;
    uint2 hp, lp;
    hp.x = *(uint32_t*)&h0; hp.y = *(uint32_t*)&h1;
    lp.x = *(uint32_t*)&l0; lp.y = *(uint32_t*)&l1;
    *(uint2*)(tile + row * 128 + ((c ^ sw) << 4) + h) = hp;
    *(uint2*)(tile + row * 128 + (((c + 4) ^ sw) << 4) + h) = lp;
}

// fp32 -> fp16 hi only (B always; MODE 1 A)
__device__ __forceinline__ void sts_hi(char* tile, int row, int k4, float4 v) {
    __half2 h0, h1;
    h0.x = __float2half_rn(v.x); h0.y = __float2half_rn(v.y);
    h1.x = __float2half_rn(v.z); h1.y = __float2half_rn(v.w);
    const int c = k4 >> 1;
    const int h = (k4 & 1) * 8;
    const int sw = row & 7;
    uint2 hp;
    hp.x = *(uint32_t*)&h0; hp.y = *(uint32_t*)&h1;
    *(uint2*)(tile + row * 128 + ((c ^ sw) << 4) + h) = hp;
}

template <int MODE>
__global__ __launch_bounds__(GT) void gemm_mma(
    const void* __restrict__ Av, long lda, long sAb, long sAh,
    const float* __restrict__ B, long ldb, long sBb, long sBh,
    float* __restrict__ C, long ldc, long sCb, long sCh,
    int K, int hdiv, float scale)
{
    extern __shared__ char sm[];

    const int t = threadIdx.x;
    const int lane = t & 31;
    const int wid = t >> 5;
    const int wm = wid >> 1;          // 0..3
    const int wn = wid & 1;           // 0..1
    const int zb = blockIdx.z / hdiv, zh = blockIdx.z % hdiv;

    const float* Ab = (MODE != 2)
        ? (const float*)Av + (size_t)zb * sAb + (size_t)zh * sAh
              + (size_t)(blockIdx.y * 128) * lda
        : nullptr;
    const __half* Ahp = (MODE == 2)
        ? (const __half*)Av + (size_t)zb * sAb + (size_t)zh * sAh
              + (size_t)(blockIdx.y * 128) * lda
        : nullptr;
    const float* Bb = B + (size_t)zb * sBb + (size_t)zh * sBh
                        + (size_t)(blockIdx.x * 128) * ldb;
    float* Cb = C + (size_t)zb * sCb + (size_t)zh * sCh
                  + (size_t)(blockIdx.y * 128) * ldc + (size_t)(blockIdx.x * 128);

    const int sub = lane >> 3;        // 0..3
    const int rin = lane & 7;

    const int k4 = t & 7;             // float4 index within 32-float slab (fp32 paths)
    const int rg = t >> 3;            // row group 0..31
    const int c2 = t & 3;             // 16B chunk within 64B hi region (MODE 2)
    const int rh = t >> 2;            // row 0..63 (MODE 2; rows rh, rh+64)

    float acc[2][8][4];
#pragma unroll
    for (int i = 0; i < 2; i++)
#pragma unroll
        for (int j = 0; j < 8; j++)
#pragma unroll
            for (int q = 0; q < 4; q++) acc[i][j][q] = 0.f;

    const int NC = K / BKC;
    float4 ra[4], rb[4];
    uint4 ra2[2];

    // ---- prologue: load + store chunk 0 into stage 0 ----
    if (MODE != 2) {
#pragma unroll
        for (int u = 0; u < 4; u++)
            ra[u] = *(const float4*)(Ab + (size_t)(rg + u * 32) * lda + k4 * 4);
    } else {
#pragma unroll
        for (int u = 0; u < 2; u++)
            ra2[u] = *(const uint4*)(Ahp + (size_t)(rh + u * 64) * lda + c2 * 8);
    }
#pragma unroll
    for (int u = 0; u < 4; u++)
        rb[u] = *(const float4*)(Bb + (size_t)(rg + u * 32) * ldb + k4 * 4);
    {
        char* As = sm;
        char* Bs = sm + 16384;
        if (MODE == 0) {
#pragma unroll
            for (int u = 0; u < 4; u++) sts_split(As, rg + u * 32, k4, ra[u]);
        } else if (MODE == 1) {
#pragma unroll
            for (int u = 0; u < 4; u++) sts_hi(As, rg + u * 32, k4, ra[u]);
        } else {
#pragma unroll
            for (int u = 0; u < 2; u++) {
                int row = rh + u * 64;
                *(uint4*)(As + row * 128 + (((c2) ^ (row & 7)) << 4)) = ra2[u];
            }
        }
#pragma unroll
        for (int u = 0; u < 4; u++) sts_hi(Bs, rg + u * 32, k4, rb[u]);
    }

    for (int c = 0; c < NC; c++) {
        if (c + 1 < NC) {
            const int kt = (c + 1) * BKC;
            if (MODE != 2) {
#pragma unroll
                for (int u = 0; u < 4; u++)
                    ra[u] = *(const float4*)(Ab + (size_t)(rg + u * 32) * lda + kt + k4 * 4);
            } else {
#pragma unroll
                for (int u = 0; u < 2; u++)
                    ra2[u] = *(const uint4*)(Ahp + (size_t)(rh + u * 64) * lda + kt + c2 * 8);
            }
#pragma unroll
            for (int u = 0; u < 4; u++)
                rb[u] = *(const float4*)(Bb + (size_t)(rg + u * 32) * ldb + kt + k4 * 4);
        }
        __syncthreads();

        char* As = sm + (c & 1) * STAGE_BYTES;
        char* Bs = As + 16384;
        const uint32_t sA = smaddr(As);
        const uint32_t sB = smaddr(Bs);

#pragma unroll
        for (int ks = 0; ks < 2; ks++) {
            uint32_t Ah[2][4], Al[2][4], Bh[4][4];
#pragma unroll
            for (int i = 0; i < 2; i++) {
                int arow = wm * 32 + i * 16 + rin + (sub & 1) * 8;
                int swz = arow & 7;
                int ch = 2 * ks + (sub >> 1);
                ldsm4(sA + arow * 128 + ((ch ^ swz) << 4), Ah[i]);
                if (MODE == 0)
                    ldsm4(sA + arow * 128 + (((ch + 4) ^ swz) << 4), Al[i]);
            }
#pragma unroll
            for (int p = 0; p < 4; p++) {
                int brow = wn * 64 + p * 16 + rin + (sub >> 1) * 8;
                int swz = brow & 7;
                int ch = 2 * ks + (sub & 1);
                ldsm4(sB + brow * 128 + ((ch ^ swz) << 4), Bh[p]);
            }
#pragma unroll
            for (int i = 0; i < 2; i++)
#pragma unroll
                for (int p = 0; p < 4; p++) {
                    mma16816(acc[i][2 * p + 0], Ah[i], &Bh[p][0]);
                    mma16816(acc[i][2 * p + 1], Ah[i], &Bh[p][2]);
                    if (MODE == 0) {
                        mma16816(acc[i][2 * p + 0], Al[i], &Bh[p][0]);
                        mma16816(acc[i][2 * p + 1], Al[i], &Bh[p][2]);
                    }
                }
        }

        if (c + 1 < NC) {
            char* An = sm + ((c + 1) & 1) * STAGE_BYTES;
            char* Bn = An + 16384;
            if (MODE == 0) {
#pragma unroll
                for (int u = 0; u < 4; u++) sts_split(An, rg + u * 32, k4, ra[u]);
            } else if (MODE == 1) {
#pragma unroll
                for (int u = 0; u < 4; u++) sts_hi(An, rg + u * 32, k4, ra[u]);
            } else {
#pragma unroll
                for (int u = 0; u < 2; u++) {
                    int row = rh + u * 64;
                    *(uint4*)(An + row * 128 + (((c2) ^ (row & 7)) << 4)) = ra2[u];
                }
            }
#pragma unroll
            for (int u = 0; u < 4; u++) sts_hi(Bn, rg + u * 32, k4, rb[u]);
        }
    }

    // epilogue: direct STG
#pragma unroll
    for (int i = 0; i < 2; i++) {
        int r = wm * 32 + i * 16 + (lane >> 2);
#pragma unroll
        for (int j = 0; j < 8; j++) {
            int cc = wn * 64 + j * 8 + (lane & 3) * 2;
            float2 v0, v1;
            v0.x = acc[i][j][0] * scale; v0.y = acc[i][j][1] * scale;
            v1.x = acc[i][j][2] * scale; v1.y = acc[i][j][3] * scale;
            *(float2*)&Cb[(size_t)r * ldc + cc] = v0;
            *(float2*)&Cb[(size_t)(r + 8) * ldc + cc] = v1;
        }
    }
}

// ---------------- fp32 transpose: out[z][C][R] = in[z][R][C] ---------------
__global__ __launch_bounds__(256) void transpose_k(
    const float* __restrict__ in, float* __restrict__ out, int R, int C)
{
    __shared__ float tile[32][33];
    size_t zo = (size_t)blockIdx.z * R * C;
    int x = blockIdx.x * 32 + threadIdx.x;
    int y0 = blockIdx.y * 32;
#pragma unroll
    for (int i = threadIdx.y; i < 32; i += 8)
        tile[i][threadIdx.x] = in[zo + (size_t)(y0 + i) * C + x];
    __syncthreads();
    int xo = blockIdx.y * 32 + threadIdx.x;
    int yo0 = blockIdx.x * 32;
#pragma unroll
    for (int i = threadIdx.y; i < 32; i += 8)
        out[zo + (size_t)(yo0 + i) * R + xo] = tile[threadIdx.x][i];
}

// ---------------- row softmax (fp32 in, fp16 out) --------------------------
__global__ __launch_bounds__(256) void softmax_k(
    const float* __restrict__ S, __half* __restrict__ P)
{
    __shared__ float redm[8];
    __shared__ float reds[8];
    const float* p = S + (size_t)blockIdx.x * SS;
    __half* po = P + (size_t)blockIdx.x * SS;
    const int t = threadIdx.x;

    float4 v = *(const float4*)(p + t * 4);
    float m = fmaxf(fmaxf(v.x, v.y), fmaxf(v.z, v.w));
#pragma unroll
    for (int o = 16; o; o >>= 1) m = fmaxf(m, __shfl_xor_sync(~0u, m, o));
    if ((t & 31) == 0) redm[t >> 5] = m;
    __syncthreads();
    float M = redm[0];
#pragma unroll
    for (int i = 1; i < 8; i++) M = fmaxf(M, redm[i]);

    float4 e;
    e.x = __expf(v.x - M); e.y = __expf(v.y - M);
    e.z = __expf(v.z - M); e.w = __expf(v.w - M);
    float s = e.x + e.y + e.z + e.w;
#pragma unroll
    for (int o = 16; o; o >>= 1) s += __shfl_xor_sync(~0u, s, o);
    if ((t & 31) == 0) reds[t >> 5] = s;
    __syncthreads();
    float Sum = 0.f;
#pragma unroll
    for (int i = 0; i < 8; i++) Sum += reds[i];
    float inv = 1.0f / Sum;

    __half2 h0, h1;
    h0 = __floats2half2_rn(e.x * inv, e.y * inv);
    h1 = __floats2half2_rn(e.z * inv, e.w * inv);
    *(uint2*)(po + t * 4) = make_uint2(*(uint32_t*)&h0, *(uint32_t*)&h1);
}

// ---------------- launch ----------------------------------------------------
extern "C" void kernel_launch(void* const* d_in, const int* in_sizes, int n_in,
                              void* d_out, int out_size)
{
    const float* inq  = (const float*)d_in[0];
    const float* inkv = (const float*)d_in[1];
    const float* Wq   = (const float*)d_in[2];
    const float* Wk   = (const float*)d_in[3];
    const float* Wv   = (const float*)d_in[4];
    const float* Wo   = (const float*)d_in[5];
    float* out = (float*)d_out;

    float *pQ, *pK, *pV, *pVt, *pC, *pWt, *pS;
    __half* pP;
    cudaGetSymbolAddress((void**)&pQ,  g_Q);
    cudaGetSymbolAddress((void**)&pK,  g_K);
    cudaGetSymbolAddress((void**)&pV,  g_V);
    cudaGetSymbolAddress((void**)&pVt, g_Vt);
    cudaGetSymbolAddress((void**)&pC,  g_C);
    cudaGetSymbolAddress((void**)&pWt, g_Wt);
    cudaGetSymbolAddress((void**)&pS,  g_S);
    cudaGetSymbolAddress((void**)&pP,  g_P);
    float* pWtq = pWt;
    float* pWtk = pWt + (size_t)DD * DD;
    float* pWtv = pWt + (size_t)2 * DD * DD;
    float* pWto = pWt + (size_t)3 * DD * DD;

    cudaFuncSetAttribute(gemm_mma<0>, cudaFuncAttributeMaxDynamicSharedMemorySize, GEMM_SMEM);
    cudaFuncSetAttribute(gemm_mma<1>, cudaFuncAttributeMaxDynamicSharedMemorySize, GEMM_SMEM);
    cudaFuncSetAttribute(gemm_mma<2>, cudaFuncAttributeMaxDynamicSharedMemorySize, GEMM_SMEM);

    const float qscale = 1.0f / sqrtf((float)HD);
    dim3 tb(32, 8);

    // transpose weights to [N][K]
    transpose_k<<<dim3(DD / 32, DD / 32, 1), tb>>>(Wq, pWtq, DD, DD);
    transpose_k<<<dim3(DD / 32, DD / 32, 1), tb>>>(Wk, pWtk, DD, DD);
    transpose_k<<<dim3(DD / 32, DD / 32, 1), tb>>>(Wv, pWtv, DD, DD);
    transpose_k<<<dim3(DD / 32, DD / 32, 1), tb>>>(Wo, pWto, DD, DD);

    // projections (2-pass split)
    dim3 pg(DD / 128, MTOK / 128, 1);   // (16, 64)
    gemm_mma<0><<<pg, GT, GEMM_SMEM>>>(inq,  DD, 0, 0, pWtq, DD, 0, 0, pQ, DD, 0, 0, DD, 1, qscale);
    gemm_mma<0><<<pg, GT, GEMM_SMEM>>>(inkv, DD, 0, 0, pWtk, DD, 0, 0, pK, DD, 0, 0, DD, 1, 1.0f);
    gemm_mma<0><<<pg, GT, GEMM_SMEM>>>(inkv, DD, 0, 0, pWtv, DD, 0, 0, pV, DD, 0, 0, DD, 1, 1.0f);

    // per-batch V transpose: [b][1024][2048] -> [b][2048][1024]
    transpose_k<<<dim3(DD / 32, SS / 32, BB), tb>>>(pV, pVt, SS, DD);

    // scores (1-pass): S[b,h][q][k] = Q . K^T over d (K=128)
    dim3 sg(SS / 128, SS / 128, BHN);   // (8, 8, 128)
    gemm_mma<1><<<sg, GT, GEMM_SMEM>>>(
        pQ, DD, (long)SS * DD, HD,
        pK, DD, (long)SS * DD, HD,
        pS, SS, (long)HH * SS * SS, (long)SS * SS,
        HD, HH, 1.0f);

    // softmax: fp32 scores -> fp16 probs
    softmax_k<<<(unsigned)((size_t)BHN * SS), 256>>>(pS, pP);

    // ctx (1-pass, fp16 A): C[b][q][h*128+d] = P . Vt^T over k (K=1024)
    dim3 cg(HD / 128, SS / 128, BHN);   // (1, 8, 128)
    gemm_mma<2><<<cg, GT, GEMM_SMEM>>>(
        pP, SS, (long)HH * SS * SS, (long)SS * SS,
        pVt, SS, (long)DD * SS, (long)HD * SS,
        pC, DD, (long)SS * DD, HD,
        SS, HH, 1.0f);

    // output projection (2-pass split)
    gemm_mma<0><<<pg, GT, GEMM_SMEM>>>(pC, DD, 0, 0, pWto, DD, 0, 0, out, DD, 0, 0, DD, 1, 1.0f);
}

// round 7
// speedup vs baseline: 3.9351x; 1.3254x over previous
#include <cuda_runtime.h>
#include <cuda_fp16.h>
#include <stdint.h>
#include <math.h>

// Problem dims (fixed)
#define BB 8
#define SS 1024
#define DD 2048
#define HH 16
#define HD 128
#define MTOK (BB * SS)     // 8192
#define BHN (BB * HH)      // 128 batch-heads

// ---------------- scratch (device globals; allocation-free) ----------------
__device__ __half g_Qh[(size_t)MTOK * DD];     // fp16 Q (pre-scaled)
__device__ __half g_Kh[(size_t)MTOK * DD];
__device__ __half g_Vh[(size_t)MTOK * DD];
__device__ float  g_C [(size_t)MTOK * DD];     // attention context (fp32)
__device__ float  g_Wt[4][(size_t)DD * DD];    // transposed weights (N-major)

// ---------------- common PTX helpers ---------------------------------------
__device__ __forceinline__ uint32_t smaddr(const void* p) {
    uint32_t a;
    asm("{ .reg .u64 t; cvta.to.shared.u64 t, %1; cvt.u32.u64 %0, t; }"
        : "=r"(a) : "l"(p));
    return a;
}
__device__ __forceinline__ void ldsm4(uint32_t addr, uint32_t* r) {
    asm volatile("ldmatrix.sync.aligned.m8n8.x4.shared.b16 {%0,%1,%2,%3}, [%4];"
                 : "=r"(r[0]), "=r"(r[1]), "=r"(r[2]), "=r"(r[3]) : "r"(addr));
}
__device__ __forceinline__ void ldsm4t(uint32_t addr, uint32_t* r) {
    asm volatile("ldmatrix.sync.aligned.m8n8.x4.trans.shared.b16 {%0,%1,%2,%3}, [%4];"
                 : "=r"(r[0]), "=r"(r[1]), "=r"(r[2]), "=r"(r[3]) : "r"(addr));
}
__device__ __forceinline__ void mma16816(float* c, const uint32_t* a, const uint32_t* b) {
    asm volatile(
        "mma.sync.aligned.m16n8k16.row.col.f32.f16.f16.f32 "
        "{%0,%1,%2,%3},{%4,%5,%6,%7},{%8,%9},{%0,%1,%2,%3};"
        : "+f"(c[0]), "+f"(c[1]), "+f"(c[2]), "+f"(c[3])
        : "r"(a[0]), "r"(a[1]), "r"(a[2]), "r"(a[3]), "r"(b[0]), "r"(b[1]));
}
__device__ __forceinline__ void cpasync16(uint32_t dst, const void* src) {
    asm volatile("cp.async.ca.shared.global [%0], [%1], 16;"
                 :: "r"(dst), "l"(src) : "memory");
}

// ---------------- mma.sync projection GEMM (fp16 2-pass A split) ------------
// D[M,N] = scale * A[M,K] @ B[N,K]^T ; A,B fp32. OUT16: D written as fp16.
#define GT 256
#define BKC 32
#define STAGE_BYTES 32768
#define GEMM_SMEM (2 * STAGE_BYTES)

__device__ __forceinline__ void sts_split(char* tile, int row, int k4, float4 v) {
    __half hx = __float2half_rn(v.x), hy = __float2half_rn(v.y);
    __half hz = __float2half_rn(v.z), hw = __float2half_rn(v.w);
    __half2 h0, h1, l0, l1;
    h0.x = hx; h0.y = hy; h1.x = hz; h1.y = hw;
    l0.x = __float2half_rn(v.x - __half2float(hx));
    l0.y = __float2half_rn(v.y - __half2float(hy));
    l1.x = __float2half_rn(v.z - __half2float(hz));
    l1.y = __float2half_rn(v.w - __half2float(hw));
    const int c = k4 >> 1;
    const int h = (k4 & 1) * 8;
    const int sw = row & 7;
    uint2 hp, lp;
    hp.x = *(uint32_t*)&h0; hp.y = *(uint32_t*)&h1;
    lp.x = *(uint32_t*)&l0; lp.y = *(uint32_t*)&l1;
    *(uint2*)(tile + row * 128 + ((c ^ sw) << 4) + h) = hp;
    *(uint2*)(tile + row * 128 + (((c + 4) ^ sw) << 4) + h) = lp;
}
__device__ __forceinline__ void sts_hi(char* tile, int row, int k4, float4 v) {
    __half2 h0, h1;
    h0.x = __float2half_rn(v.x); h0.y = __float2half_rn(v.y);
    h1.x = __float2half_rn(v.z); h1.y = __float2half_rn(v.w);
    const int c = k4 >> 1;
    const int h = (k4 & 1) * 8;
    const int sw = row & 7;
    uint2 hp;
    hp.x = *(uint32_t*)&h0; hp.y = *(uint32_t*)&h1;
    *(uint2*)(tile + row * 128 + ((c ^ sw) << 4) + h) = hp;
}

template <int OUT16>
__global__ __launch_bounds__(GT) void gemm_mma(
    const float* __restrict__ A, long lda,
    const float* __restrict__ B, long ldb,
    void* __restrict__ Cv, long ldc,
    int K, float scale)
{
    extern __shared__ char sm[];

    const int t = threadIdx.x;
    const int lane = t & 31;
    const int wid = t >> 5;
    const int wm = wid >> 1;
    const int wn = wid & 1;

    const float* Ab = A + (size_t)(blockIdx.y * 128) * lda;
    const float* Bb = B + (size_t)(blockIdx.x * 128) * ldb;

    const int sub = lane >> 3;
    const int rin = lane & 7;
    const int k4 = t & 7;
    const int rg = t >> 3;

    float acc[2][8][4];
#pragma unroll
    for (int i = 0; i < 2; i++)
#pragma unroll
        for (int j = 0; j < 8; j++)
#pragma unroll
            for (int q = 0; q < 4; q++) acc[i][j][q] = 0.f;

    const int NC = K / BKC;
    float4 ra[4], rb[4];

#pragma unroll
    for (int u = 0; u < 4; u++) {
        ra[u] = *(const float4*)(Ab + (size_t)(rg + u * 32) * lda + k4 * 4);
        rb[u] = *(const float4*)(Bb + (size_t)(rg + u * 32) * ldb + k4 * 4);
    }
    {
        char* As = sm;
        char* Bs = sm + 16384;
#pragma unroll
        for (int u = 0; u < 4; u++) {
            sts_split(As, rg + u * 32, k4, ra[u]);
            sts_hi(Bs, rg + u * 32, k4, rb[u]);
        }
    }

    for (int c = 0; c < NC; c++) {
        if (c + 1 < NC) {
            const int kt = (c + 1) * BKC;
#pragma unroll
            for (int u = 0; u < 4; u++) {
                ra[u] = *(const float4*)(Ab + (size_t)(rg + u * 32) * lda + kt + k4 * 4);
                rb[u] = *(const float4*)(Bb + (size_t)(rg + u * 32) * ldb + kt + k4 * 4);
            }
        }
        __syncthreads();

        char* As = sm + (c & 1) * STAGE_BYTES;
        char* Bs = As + 16384;
        const uint32_t sA = smaddr(As);
        const uint32_t sB = smaddr(Bs);

#pragma unroll
        for (int ks = 0; ks < 2; ks++) {
            uint32_t Ah[2][4], Al[2][4], Bh[4][4];
#pragma unroll
            for (int i = 0; i < 2; i++) {
                int arow = wm * 32 + i * 16 + rin + (sub & 1) * 8;
                int swz = arow & 7;
                int ch = 2 * ks + (sub >> 1);
                ldsm4(sA + arow * 128 + ((ch ^ swz) << 4), Ah[i]);
                ldsm4(sA + arow * 128 + (((ch + 4) ^ swz) << 4), Al[i]);
            }
#pragma unroll
            for (int p = 0; p < 4; p++) {
                int brow = wn * 64 + p * 16 + rin + (sub >> 1) * 8;
                int swz = brow & 7;
                int ch = 2 * ks + (sub & 1);
                ldsm4(sB + brow * 128 + ((ch ^ swz) << 4), Bh[p]);
            }
#pragma unroll
            for (int i = 0; i < 2; i++)
#pragma unroll
                for (int p = 0; p < 4; p++) {
                    mma16816(acc[i][2 * p + 0], Ah[i], &Bh[p][0]);
                    mma16816(acc[i][2 * p + 1], Ah[i], &Bh[p][2]);
                    mma16816(acc[i][2 * p + 0], Al[i], &Bh[p][0]);
                    mma16816(acc[i][2 * p + 1], Al[i], &Bh[p][2]);
                }
        }

        if (c + 1 < NC) {
            char* An = sm + ((c + 1) & 1) * STAGE_BYTES;
            char* Bn = An + 16384;
#pragma unroll
            for (int u = 0; u < 4; u++) {
                sts_split(An, rg + u * 32, k4, ra[u]);
                sts_hi(Bn, rg + u * 32, k4, rb[u]);
            }
        }
    }

    // epilogue
#pragma unroll
    for (int i = 0; i < 2; i++) {
        int r = blockIdx.y * 128 + wm * 32 + i * 16 + (lane >> 2);
#pragma unroll
        for (int j = 0; j < 8; j++) {
            int cc = blockIdx.x * 128 + wn * 64 + j * 8 + (lane & 3) * 2;
            if (OUT16) {
                __half* Co = (__half*)Cv;
                __half2 h0 = __floats2half2_rn(acc[i][j][0] * scale, acc[i][j][1] * scale);
                __half2 h1 = __floats2half2_rn(acc[i][j][2] * scale, acc[i][j][3] * scale);
                *(uint32_t*)&Co[(size_t)r * ldc + cc] = *(uint32_t*)&h0;
                *(uint32_t*)&Co[(size_t)(r + 8) * ldc + cc] = *(uint32_t*)&h1;
            } else {
                float* Co = (float*)Cv;
                float2 v0, v1;
                v0.x = acc[i][j][0] * scale; v0.y = acc[i][j][1] * scale;
                v1.x = acc[i][j][2] * scale; v1.y = acc[i][j][3] * scale;
                *(float2*)&Co[(size_t)r * ldc + cc] = v0;
                *(float2*)&Co[(size_t)(r + 8) * ldc + cc] = v1;
            }
        }
    }
}

// ---------------- fused flash attention -------------------------------------
// grid (SS/128, HH, BB), 256 threads (8 warps x 16 q-rows).
// SMEM: Q 32KB | K[2] 2x32KB | V[2] 2x32KB = 160KB. fp16 tiles, 256B rows,
// 16B-chunk swizzle: phys_chunk = c ^ (row & 7).
#define FA_SMEM (32768 + 4 * 32768)

__device__ __forceinline__ uint32_t sw_off(int row, int c) {
    return (uint32_t)(row * 256 + ((c ^ (row & 7)) << 4));
}

__global__ __launch_bounds__(256, 1) void flash_attn(
    const __half* __restrict__ Q, const __half* __restrict__ K,
    const __half* __restrict__ V, float* __restrict__ O)
{
    extern __shared__ char sm[];
    const uint32_t qs = smaddr(sm);
    const uint32_t ks0 = qs + 32768;
    const uint32_t vs0 = qs + 98304;

    const int t = threadIdx.x;
    const int lane = t & 31;
    const int wid = t >> 5;
    const int q0 = blockIdx.x * 128;
    const int hd0 = blockIdx.y * HD;
    const int tokB = blockIdx.z * SS;

    const __half* Kg = K + (size_t)tokB * DD + hd0;
    const __half* Vg = V + (size_t)tokB * DD + hd0;

    // ---- issue K/V tile loads for tile 0 ----
    const int lr = t >> 4;          // 0..15 (row group for copies)
    const int lc = t & 15;          // chunk 0..15
    {
        const __half* kg = Kg;
        const __half* vg = Vg;
#pragma unroll
        for (int j = 0; j < 8; j++) {
            int row = lr + j * 16;
            cpasync16(ks0 + sw_off(row, lc), kg + (size_t)row * DD + lc * 8);
        }
#pragma unroll
        for (int j = 0; j < 8; j++) {
            int row = lr + j * 16;
            cpasync16(vs0 + sw_off(row, lc), vg + (size_t)row * DD + lc * 8);
        }
        asm volatile("cp.async.commit_group;" ::: "memory");
    }

    // ---- stage Q tile (fp16, swizzled) ----
    {
        const __half* qg = Q + (size_t)(tokB + q0) * DD + hd0;
#pragma unroll
        for (int j = 0; j < 8; j++) {
            int row = lr + j * 16;
            uint4 v = *(const uint4*)(qg + (size_t)row * DD + lc * 8);
            *(uint4*)(sm + sw_off(row, lc)) = v;
        }
    }
    __syncthreads();

    // ---- Q fragments (16 rows per warp, K=128 -> 8 frags of 4 regs) ----
    uint32_t Qfr[8][4];
    {
        const int rloc = wid * 16 + (lane & 15);
#pragma unroll
        for (int kk = 0; kk < 8; kk++) {
            int c = 2 * kk + (lane >> 4);
            ldsm4(qs + sw_off(rloc, c), Qfr[kk]);
        }
    }

    float accO[16][4];
#pragma unroll
    for (int nt = 0; nt < 16; nt++)
#pragma unroll
        for (int q = 0; q < 4; q++) accO[nt][q] = 0.f;
    float m0 = -1e30f, m1 = -1e30f, l0 = 0.f, l1 = 0.f;

    for (int it = 0; it < SS / 128; it++) {
        const uint32_t ksb = ks0 + (it & 1) * 32768;
        const uint32_t vsb = vs0 + (it & 1) * 32768;

        if (it + 1 < SS / 128) {
            const uint32_t kn = ks0 + ((it + 1) & 1) * 32768;
            const uint32_t vn = vs0 + ((it + 1) & 1) * 32768;
            const __half* kg = Kg + (size_t)(it + 1) * 128 * DD;
            const __half* vg = Vg + (size_t)(it + 1) * 128 * DD;
#pragma unroll
            for (int j = 0; j < 8; j++) {
                int row = lr + j * 16;
                cpasync16(kn + sw_off(row, lc), kg + (size_t)row * DD + lc * 8);
            }
#pragma unroll
            for (int j = 0; j < 8; j++) {
                int row = lr + j * 16;
                cpasync16(vn + sw_off(row, lc), vg + (size_t)row * DD + lc * 8);
            }
            asm volatile("cp.async.commit_group;" ::: "memory");
            asm volatile("cp.async.wait_group 1;" ::: "memory");
        } else {
            asm volatile("cp.async.wait_group 0;" ::: "memory");
        }
        __syncthreads();

        // ---- S = Q @ K^T : per warp 16x128, accS[nt][4] ----
        float accS[16][4];
#pragma unroll
        for (int nt = 0; nt < 16; nt++)
#pragma unroll
            for (int q = 0; q < 4; q++) accS[nt][q] = 0.f;

#pragma unroll
        for (int np = 0; np < 8; np++) {
            const int krow = np * 16 + (lane & 7) + ((lane >> 4) << 3);
#pragma unroll
            for (int kk = 0; kk < 8; kk++) {
                uint32_t Bf[4];
                int c = 2 * kk + ((lane >> 3) & 1);
                ldsm4(ksb + sw_off(krow, c), Bf);
                mma16816(accS[2 * np + 0], Qfr[kk], &Bf[0]);
                mma16816(accS[2 * np + 1], Qfr[kk], &Bf[2]);
            }
        }

        // ---- online softmax (rows r0 = regs 0,1 ; r1 = regs 2,3) ----
        float mx0 = -1e30f, mx1 = -1e30f;
#pragma unroll
        for (int nt = 0; nt < 16; nt++) {
            mx0 = fmaxf(mx0, fmaxf(accS[nt][0], accS[nt][1]));
            mx1 = fmaxf(mx1, fmaxf(accS[nt][2], accS[nt][3]));
        }
        mx0 = fmaxf(mx0, __shfl_xor_sync(~0u, mx0, 1));
        mx0 = fmaxf(mx0, __shfl_xor_sync(~0u, mx0, 2));
        mx1 = fmaxf(mx1, __shfl_xor_sync(~0u, mx1, 1));
        mx1 = fmaxf(mx1, __shfl_xor_sync(~0u, mx1, 2));

        float mn0 = fmaxf(m0, mx0), mn1 = fmaxf(m1, mx1);
        float a0 = __expf(m0 - mn0), a1 = __expf(m1 - mn1);
        m0 = mn0; m1 = mn1;

        float s0 = 0.f, s1 = 0.f;
#pragma unroll
        for (int nt = 0; nt < 16; nt++) {
            accS[nt][0] = __expf(accS[nt][0] - m0); s0 += accS[nt][0];
            accS[nt][1] = __expf(accS[nt][1] - m0); s0 += accS[nt][1];
            accS[nt][2] = __expf(accS[nt][2] - m1); s1 += accS[nt][2];
            accS[nt][3] = __expf(accS[nt][3] - m1); s1 += accS[nt][3];
        }
        s0 += __shfl_xor_sync(~0u, s0, 1); s0 += __shfl_xor_sync(~0u, s0, 2);
        s1 += __shfl_xor_sync(~0u, s1, 1); s1 += __shfl_xor_sync(~0u, s1, 2);
        l0 = l0 * a0 + s0;
        l1 = l1 * a1 + s1;

#pragma unroll
        for (int nt = 0; nt < 16; nt++) {
            accO[nt][0] *= a0; accO[nt][1] *= a0;
            accO[nt][2] *= a1; accO[nt][3] *= a1;
        }

        // ---- O += P @ V ----
#pragma unroll
        for (int kk = 0; kk < 8; kk++) {
            uint32_t Pf[4];
            __half2 p0 = __floats2half2_rn(accS[2 * kk][0], accS[2 * kk][1]);
            __half2 p1 = __floats2half2_rn(accS[2 * kk][2], accS[2 * kk][3]);
            __half2 p2 = __floats2half2_rn(accS[2 * kk + 1][0], accS[2 * kk + 1][1]);
            __half2 p3 = __floats2half2_rn(accS[2 * kk + 1][2], accS[2 * kk + 1][3]);
            Pf[0] = *(uint32_t*)&p0; Pf[1] = *(uint32_t*)&p1;
            Pf[2] = *(uint32_t*)&p2; Pf[3] = *(uint32_t*)&p3;

            const int vrow = kk * 16 + (lane & 15);
#pragma unroll
            for (int nd = 0; nd < 8; nd++) {
                uint32_t Bf[4];
                int c = 2 * nd + (lane >> 4);
                ldsm4t(vsb + sw_off(vrow, c), Bf);
                mma16816(accO[2 * nd + 0], Pf, &Bf[0]);
                mma16816(accO[2 * nd + 1], Pf, &Bf[2]);
            }
        }
        __syncthreads();
    }

    // ---- write context (normalized) ----
    const float i0 = 1.f / l0, i1 = 1.f / l1;
    const int r0 = tokB + q0 + wid * 16 + (lane >> 2);
#pragma unroll
    for (int nt = 0; nt < 16; nt++) {
        int d = hd0 + nt * 8 + (lane & 3) * 2;
        float2 v0, v1;
        v0.x = accO[nt][0] * i0; v0.y = accO[nt][1] * i0;
        v1.x = accO[nt][2] * i1; v1.y = accO[nt][3] * i1;
        *(float2*)&O[(size_t)r0 * DD + d] = v0;
        *(float2*)&O[(size_t)(r0 + 8) * DD + d] = v1;
    }
}

// ---------------- fp32 transpose -------------------------------------------
__global__ __launch_bounds__(256) void transpose_k(
    const float* __restrict__ in, float* __restrict__ out, int R, int C)
{
    __shared__ float tile[32][33];
    int x = blockIdx.x * 32 + threadIdx.x;
    int y0 = blockIdx.y * 32;
#pragma unroll
    for (int i = threadIdx.y; i < 32; i += 8)
        tile[i][threadIdx.x] = in[(size_t)(y0 + i) * C + x];
    __syncthreads();
    int xo = blockIdx.y * 32 + threadIdx.x;
    int yo0 = blockIdx.x * 32;
#pragma unroll
    for (int i = threadIdx.y; i < 32; i += 8)
        out[(size_t)(yo0 + i) * R + xo] = tile[threadIdx.x][i];
}

// ---------------- launch ----------------------------------------------------
extern "C" void kernel_launch(void* const* d_in, const int* in_sizes, int n_in,
                              void* d_out, int out_size)
{
    const float* inq  = (const float*)d_in[0];
    const float* inkv = (const float*)d_in[1];
    const float* Wq   = (const float*)d_in[2];
    const float* Wk   = (const float*)d_in[3];
    const float* Wv   = (const float*)d_in[4];
    const float* Wo   = (const float*)d_in[5];
    float* out = (float*)d_out;

    __half *pQh, *pKh, *pVh;
    float *pC, *pWt;
    cudaGetSymbolAddress((void**)&pQh, g_Qh);
    cudaGetSymbolAddress((void**)&pKh, g_Kh);
    cudaGetSymbolAddress((void**)&pVh, g_Vh);
    cudaGetSymbolAddress((void**)&pC,  g_C);
    cudaGetSymbolAddress((void**)&pWt, g_Wt);
    float* pWtq = pWt;
    float* pWtk = pWt + (size_t)DD * DD;
    float* pWtv = pWt + (size_t)2 * DD * DD;
    float* pWto = pWt + (size_t)3 * DD * DD;

    cudaFuncSetAttribute(gemm_mma<0>, cudaFuncAttributeMaxDynamicSharedMemorySize, GEMM_SMEM);
    cudaFuncSetAttribute(gemm_mma<1>, cudaFuncAttributeMaxDynamicSharedMemorySize, GEMM_SMEM);
    cudaFuncSetAttribute(flash_attn, cudaFuncAttributeMaxDynamicSharedMemorySize, FA_SMEM);

    const float qscale = 1.0f / sqrtf((float)HD);
    dim3 tb(32, 8);

    // transpose weights to [N][K]
    transpose_k<<<dim3(DD / 32, DD / 32), tb>>>(Wq, pWtq, DD, DD);
    transpose_k<<<dim3(DD / 32, DD / 32), tb>>>(Wk, pWtk, DD, DD);
    transpose_k<<<dim3(DD / 32, DD / 32), tb>>>(Wv, pWtv, DD, DD);
    transpose_k<<<dim3(DD / 32, DD / 32), tb>>>(Wo, pWto, DD, DD);

    // projections -> fp16 Q/K/V
    dim3 pg(DD / 128, MTOK / 128);
    gemm_mma<1><<<pg, GT, GEMM_SMEM>>>(inq,  DD, pWtq, DD, pQh, DD, DD, qscale);
    gemm_mma<1><<<pg, GT, GEMM_SMEM>>>(inkv, DD, pWtk, DD, pKh, DD, DD, 1.0f);
    gemm_mma<1><<<pg, GT, GEMM_SMEM>>>(inkv, DD, pWtv, DD, pVh, DD, DD, 1.0f);

    // fused attention -> fp32 context
    dim3 fg(SS / 128, HH, BB);
    flash_attn<<<fg, 256, FA_SMEM>>>(pQh, pKh, pVh, pC);

    // output projection (fp32 out)
    gemm_mma<0><<<pg, GT, GEMM_SMEM>>>(pC, DD, pWto, DD, out, DD, DD, 1.0f);
}

// round 8
// speedup vs baseline: 4.3596x; 1.1079x over previous
#include <cuda_runtime.h>
#include <cuda_fp16.h>
#include <stdint.h>
#include <math.h>

// Problem dims (fixed)
#define BB 8
#define SS 1024
#define DD 2048
#define HH 16
#define HD 128
#define MTOK (BB * SS)     // 8192
#define BHN (BB * HH)      // 128 batch-heads

// ---------------- scratch (device globals; allocation-free) ----------------
__device__ __half g_Qh[(size_t)MTOK * DD];     // fp16 Q (pre-scaled)
__device__ __half g_Kh[(size_t)MTOK * DD];
__device__ __half g_Vh[(size_t)MTOK * DD];
__device__ float  g_C [(size_t)MTOK * DD];     // attention context (fp32)
__device__ float  g_Wt[4][(size_t)DD * DD];    // transposed weights (N-major)

// ---------------- common PTX helpers ---------------------------------------
__device__ __forceinline__ uint32_t smaddr(const void* p) {
    uint32_t a;
    asm("{ .reg .u64 t; cvta.to.shared.u64 t, %1; cvt.u32.u64 %0, t; }"
        : "=r"(a) : "l"(p));
    return a;
}
__device__ __forceinline__ void ldsm4(uint32_t addr, uint32_t* r) {
    asm volatile("ldmatrix.sync.aligned.m8n8.x4.shared.b16 {%0,%1,%2,%3}, [%4];"
                 : "=r"(r[0]), "=r"(r[1]), "=r"(r[2]), "=r"(r[3]) : "r"(addr));
}
__device__ __forceinline__ void ldsm4t(uint32_t addr, uint32_t* r) {
    asm volatile("ldmatrix.sync.aligned.m8n8.x4.trans.shared.b16 {%0,%1,%2,%3}, [%4];"
                 : "=r"(r[0]), "=r"(r[1]), "=r"(r[2]), "=r"(r[3]) : "r"(addr));
}
__device__ __forceinline__ void mma16816(float* c, const uint32_t* a, const uint32_t* b) {
    asm volatile(
        "mma.sync.aligned.m16n8k16.row.col.f32.f16.f16.f32 "
        "{%0,%1,%2,%3},{%4,%5,%6,%7},{%8,%9},{%0,%1,%2,%3};"
        : "+f"(c[0]), "+f"(c[1]), "+f"(c[2]), "+f"(c[3])
        : "r"(a[0]), "r"(a[1]), "r"(a[2]), "r"(a[3]), "r"(b[0]), "r"(b[1]));
}
__device__ __forceinline__ void cpasync16(uint32_t dst, const void* src) {
    asm volatile("cp.async.ca.shared.global [%0], [%1], 16;"
                 :: "r"(dst), "l"(src) : "memory");
}

// ---------------- mma.sync projection GEMM (fp16 single-pass) ---------------
// D[M,N] = scale * A[M,K] @ B[N,K]^T ; A,B fp32 rounded to fp16.
// Block tile 128x128, BK=32, 256 threads (8 warps: 4m x 2n, 32x64 per warp).
// SMEM per-operand tile: [row][64B] (hi fp16 only), chunk swizzle c ^ (row&3)
// over 4 chunks of 16B. OUT16: D written as fp16.
#define GT 256
#define BKC 32
#define TILE_BYTES 8192                 // 128 rows x 64 B
#define STAGE_BYTES (2 * TILE_BYTES)    // A + B
#define GEMM_SMEM (2 * STAGE_BYTES)     // 32 KB

__device__ __forceinline__ void sts_hi(char* tile, int row, int k4, float4 v) {
    __half2 h0, h1;
    h0.x = __float2half_rn(v.x); h0.y = __float2half_rn(v.y);
    h1.x = __float2half_rn(v.z); h1.y = __float2half_rn(v.w);
    const int c = k4 >> 1;              // 16B chunk 0..3
    const int h = (k4 & 1) * 8;
    const int sw = row & 3;
    uint2 hp;
    hp.x = *(uint32_t*)&h0; hp.y = *(uint32_t*)&h1;
    *(uint2*)(tile + row * 64 + ((c ^ sw) << 4) + h) = hp;
}

template <int OUT16>
__global__ __launch_bounds__(GT) void gemm_mma(
    const float* __restrict__ A, long lda,
    const float* __restrict__ B, long ldb,
    void* __restrict__ Cv, long ldc,
    int K, float scale)
{
    extern __shared__ char sm[];

    const int t = threadIdx.x;
    const int lane = t & 31;
    const int wid = t >> 5;
    const int wm = wid >> 1;
    const int wn = wid & 1;

    const float* Ab = A + (size_t)(blockIdx.y * 128) * lda;
    const float* Bb = B + (size_t)(blockIdx.x * 128) * ldb;

    const int sub = lane >> 3;
    const int rin = lane & 7;
    const int k4 = t & 7;
    const int rg = t >> 3;

    float acc[2][8][4];
#pragma unroll
    for (int i = 0; i < 2; i++)
#pragma unroll
        for (int j = 0; j < 8; j++)
#pragma unroll
            for (int q = 0; q < 4; q++) acc[i][j][q] = 0.f;

    const int NC = K / BKC;
    float4 ra[4], rb[4];

#pragma unroll
    for (int u = 0; u < 4; u++) {
        ra[u] = *(const float4*)(Ab + (size_t)(rg + u * 32) * lda + k4 * 4);
        rb[u] = *(const float4*)(Bb + (size_t)(rg + u * 32) * ldb + k4 * 4);
    }
    {
        char* As = sm;
        char* Bs = sm + TILE_BYTES;
#pragma unroll
        for (int u = 0; u < 4; u++) {
            sts_hi(As, rg + u * 32, k4, ra[u]);
            sts_hi(Bs, rg + u * 32, k4, rb[u]);
        }
    }

    for (int c = 0; c < NC; c++) {
        if (c + 1 < NC) {
            const int kt = (c + 1) * BKC;
#pragma unroll
            for (int u = 0; u < 4; u++) {
                ra[u] = *(const float4*)(Ab + (size_t)(rg + u * 32) * lda + kt + k4 * 4);
                rb[u] = *(const float4*)(Bb + (size_t)(rg + u * 32) * ldb + kt + k4 * 4);
            }
        }
        __syncthreads();

        char* As = sm + (c & 1) * STAGE_BYTES;
        char* Bs = As + TILE_BYTES;
        const uint32_t sA = smaddr(As);
        const uint32_t sB = smaddr(Bs);

#pragma unroll
        for (int ks = 0; ks < 2; ks++) {
            uint32_t Ah[2][4], Bh[4][4];
#pragma unroll
            for (int i = 0; i < 2; i++) {
                int arow = wm * 32 + i * 16 + rin + (sub & 1) * 8;
                int swz = arow & 3;
                int ch = 2 * ks + (sub >> 1);
                ldsm4(sA + arow * 64 + ((ch ^ swz) << 4), Ah[i]);
            }
#pragma unroll
            for (int p = 0; p < 4; p++) {
                int brow = wn * 64 + p * 16 + rin + (sub >> 1) * 8;
                int swz = brow & 3;
                int ch = 2 * ks + (sub & 1);
                ldsm4(sB + brow * 64 + ((ch ^ swz) << 4), Bh[p]);
            }
#pragma unroll
            for (int i = 0; i < 2; i++)
#pragma unroll
                for (int p = 0; p < 4; p++) {
                    mma16816(acc[i][2 * p + 0], Ah[i], &Bh[p][0]);
                    mma16816(acc[i][2 * p + 1], Ah[i], &Bh[p][2]);
                }
        }

        if (c + 1 < NC) {
            char* An = sm + ((c + 1) & 1) * STAGE_BYTES;
            char* Bn = An + TILE_BYTES;
#pragma unroll
            for (int u = 0; u < 4; u++) {
                sts_hi(An, rg + u * 32, k4, ra[u]);
                sts_hi(Bn, rg + u * 32, k4, rb[u]);
            }
        }
    }

    // epilogue
#pragma unroll
    for (int i = 0; i < 2; i++) {
        int r = blockIdx.y * 128 + wm * 32 + i * 16 + (lane >> 2);
#pragma unroll
        for (int j = 0; j < 8; j++) {
            int cc = blockIdx.x * 128 + wn * 64 + j * 8 + (lane & 3) * 2;
            if (OUT16) {
                __half* Co = (__half*)Cv;
                __half2 h0 = __floats2half2_rn(acc[i][j][0] * scale, acc[i][j][1] * scale);
                __half2 h1 = __floats2half2_rn(acc[i][j][2] * scale, acc[i][j][3] * scale);
                *(uint32_t*)&Co[(size_t)r * ldc + cc] = *(uint32_t*)&h0;
                *(uint32_t*)&Co[(size_t)(r + 8) * ldc + cc] = *(uint32_t*)&h1;
            } else {
                float* Co = (float*)Cv;
                float2 v0, v1;
                v0.x = acc[i][j][0] * scale; v0.y = acc[i][j][1] * scale;
                v1.x = acc[i][j][2] * scale; v1.y = acc[i][j][3] * scale;
                *(float2*)&Co[(size_t)r * ldc + cc] = v0;
                *(float2*)&Co[(size_t)(r + 8) * ldc + cc] = v1;
            }
        }
    }
}

// ---------------- fused flash attention -------------------------------------
// grid (SS/128, HH, BB), 256 threads (8 warps x 16 q-rows).
// SMEM: Q 32KB | K[2] 2x32KB | V[2] 2x32KB = 160KB. fp16 tiles, 256B rows,
// 16B-chunk swizzle: phys_chunk = c ^ (row & 7).
#define FA_SMEM (32768 + 4 * 32768)

__device__ __forceinline__ uint32_t sw_off(int row, int c) {
    return (uint32_t)(row * 256 + ((c ^ (row & 7)) << 4));
}

__global__ __launch_bounds__(256, 1) void flash_attn(
    const __half* __restrict__ Q, const __half* __restrict__ K,
    const __half* __restrict__ V, float* __restrict__ O)
{
    extern __shared__ char sm[];
    const uint32_t qs = smaddr(sm);
    const uint32_t ks0 = qs + 32768;
    const uint32_t vs0 = qs + 98304;

    const int t = threadIdx.x;
    const int lane = t & 31;
    const int wid = t >> 5;
    const int q0 = blockIdx.x * 128;
    const int hd0 = blockIdx.y * HD;
    const int tokB = blockIdx.z * SS;

    const __half* Kg = K + (size_t)tokB * DD + hd0;
    const __half* Vg = V + (size_t)tokB * DD + hd0;

    const int lr = t >> 4;          // 0..15 (row group for copies)
    const int lc = t & 15;          // chunk 0..15
    {
#pragma unroll
        for (int j = 0; j < 8; j++) {
            int row = lr + j * 16;
            cpasync16(ks0 + sw_off(row, lc), Kg + (size_t)row * DD + lc * 8);
        }
#pragma unroll
        for (int j = 0; j < 8; j++) {
            int row = lr + j * 16;
            cpasync16(vs0 + sw_off(row, lc), Vg + (size_t)row * DD + lc * 8);
        }
        asm volatile("cp.async.commit_group;" ::: "memory");
    }

    // ---- stage Q tile (fp16, swizzled) ----
    {
        const __half* qg = Q + (size_t)(tokB + q0) * DD + hd0;
#pragma unroll
        for (int j = 0; j < 8; j++) {
            int row = lr + j * 16;
            uint4 v = *(const uint4*)(qg + (size_t)row * DD + lc * 8);
            *(uint4*)(sm + sw_off(row, lc)) = v;
        }
    }
    __syncthreads();

    // ---- Q fragments (16 rows per warp, K=128 -> 8 frags of 4 regs) ----
    uint32_t Qfr[8][4];
    {
        const int rloc = wid * 16 + (lane & 15);
#pragma unroll
        for (int kk = 0; kk < 8; kk++) {
            int c = 2 * kk + (lane >> 4);
            ldsm4(qs + sw_off(rloc, c), Qfr[kk]);
        }
    }

    float accO[16][4];
#pragma unroll
    for (int nt = 0; nt < 16; nt++)
#pragma unroll
        for (int q = 0; q < 4; q++) accO[nt][q] = 0.f;
    float m0 = -1e30f, m1 = -1e30f, l0 = 0.f, l1 = 0.f;

    for (int it = 0; it < SS / 128; it++) {
        const uint32_t ksb = ks0 + (it & 1) * 32768;
        const uint32_t vsb = vs0 + (it & 1) * 32768;

        if (it + 1 < SS / 128) {
            const uint32_t kn = ks0 + ((it + 1) & 1) * 32768;
            const uint32_t vn = vs0 + ((it + 1) & 1) * 32768;
            const __half* kg = Kg + (size_t)(it + 1) * 128 * DD;
            const __half* vg = Vg + (size_t)(it + 1) * 128 * DD;
#pragma unroll
            for (int j = 0; j < 8; j++) {
                int row = lr + j * 16;
                cpasync16(kn + sw_off(row, lc), kg + (size_t)row * DD + lc * 8);
            }
#pragma unroll
            for (int j = 0; j < 8; j++) {
                int row = lr + j * 16;
                cpasync16(vn + sw_off(row, lc), vg + (size_t)row * DD + lc * 8);
            }
            asm volatile("cp.async.commit_group;" ::: "memory");
            asm volatile("cp.async.wait_group 1;" ::: "memory");
        } else {
            asm volatile("cp.async.wait_group 0;" ::: "memory");
        }
        __syncthreads();

        // ---- S = Q @ K^T : per warp 16x128 ----
        float accS[16][4];
#pragma unroll
        for (int nt = 0; nt < 16; nt++)
#pragma unroll
            for (int q = 0; q < 4; q++) accS[nt][q] = 0.f;

#pragma unroll
        for (int np = 0; np < 8; np++) {
            const int krow = np * 16 + (lane & 7) + ((lane >> 4) << 3);
#pragma unroll
            for (int kk = 0; kk < 8; kk++) {
                uint32_t Bf[4];
                int c = 2 * kk + ((lane >> 3) & 1);
                ldsm4(ksb + sw_off(krow, c), Bf);
                mma16816(accS[2 * np + 0], Qfr[kk], &Bf[0]);
                mma16816(accS[2 * np + 1], Qfr[kk], &Bf[2]);
            }
        }

        // ---- online softmax ----
        float mx0 = -1e30f, mx1 = -1e30f;
#pragma unroll
        for (int nt = 0; nt < 16; nt++) {
            mx0 = fmaxf(mx0, fmaxf(accS[nt][0], accS[nt][1]));
            mx1 = fmaxf(mx1, fmaxf(accS[nt][2], accS[nt][3]));
        }
        mx0 = fmaxf(mx0, __shfl_xor_sync(~0u, mx0, 1));
        mx0 = fmaxf(mx0, __shfl_xor_sync(~0u, mx0, 2));
        mx1 = fmaxf(mx1, __shfl_xor_sync(~0u, mx1, 1));
        mx1 = fmaxf(mx1, __shfl_xor_sync(~0u, mx1, 2));

        float mn0 = fmaxf(m0, mx0), mn1 = fmaxf(m1, mx1);
        float a0 = __expf(m0 - mn0), a1 = __expf(m1 - mn1);
        m0 = mn0; m1 = mn1;

        float s0 = 0.f, s1 = 0.f;
#pragma unroll
        for (int nt = 0; nt < 16; nt++) {
            accS[nt][0] = __expf(accS[nt][0] - m0); s0 += accS[nt][0];
            accS[nt][1] = __expf(accS[nt][1] - m0); s0 += accS[nt][1];
            accS[nt][2] = __expf(accS[nt][2] - m1); s1 += accS[nt][2];
            accS[nt][3] = __expf(accS[nt][3] - m1); s1 += accS[nt][3];
        }
        s0 += __shfl_xor_sync(~0u, s0, 1); s0 += __shfl_xor_sync(~0u, s0, 2);
        s1 += __shfl_xor_sync(~0u, s1, 1); s1 += __shfl_xor_sync(~0u, s1, 2);
        l0 = l0 * a0 + s0;
        l1 = l1 * a1 + s1;

#pragma unroll
        for (int nt = 0; nt < 16; nt++) {
            accO[nt][0] *= a0; accO[nt][1] *= a0;
            accO[nt][2] *= a1; accO[nt][3] *= a1;
        }

        // ---- O += P @ V ----
#pragma unroll
        for (int kk = 0; kk < 8; kk++) {
            uint32_t Pf[4];
            __half2 p0 = __floats2half2_rn(accS[2 * kk][0], accS[2 * kk][1]);
            __half2 p1 = __floats2half2_rn(accS[2 * kk][2], accS[2 * kk][3]);
            __half2 p2 = __floats2half2_rn(accS[2 * kk + 1][0], accS[2 * kk + 1][1]);
            __half2 p3 = __floats2half2_rn(accS[2 * kk + 1][2], accS[2 * kk + 1][3]);
            Pf[0] = *(uint32_t*)&p0; Pf[1] = *(uint32_t*)&p1;
            Pf[2] = *(uint32_t*)&p2; Pf[3] = *(uint32_t*)&p3;

            const int vrow = kk * 16 + (lane & 15);
#pragma unroll
            for (int nd = 0; nd < 8; nd++) {
                uint32_t Bf[4];
                int c = 2 * nd + (lane >> 4);
                ldsm4t(vsb + sw_off(vrow, c), Bf);
                mma16816(accO[2 * nd + 0], Pf, &Bf[0]);
                mma16816(accO[2 * nd + 1], Pf, &Bf[2]);
            }
        }
        __syncthreads();
    }

    // ---- write context (normalized) ----
    const float i0 = 1.f / l0, i1 = 1.f / l1;
    const int r0 = tokB + q0 + wid * 16 + (lane >> 2);
#pragma unroll
    for (int nt = 0; nt < 16; nt++) {
        int d = hd0 + nt * 8 + (lane & 3) * 2;
        float2 v0, v1;
        v0.x = accO[nt][0] * i0; v0.y = accO[nt][1] * i0;
        v1.x = accO[nt][2] * i1; v1.y = accO[nt][3] * i1;
        *(float2*)&O[(size_t)r0 * DD + d] = v0;
        *(float2*)&O[(size_t)(r0 + 8) * DD + d] = v1;
    }
}

// ---------------- fp32 transpose -------------------------------------------
__global__ __launch_bounds__(256) void transpose_k(
    const float* __restrict__ in, float* __restrict__ out, int R, int C)
{
    __shared__ float tile[32][33];
    int x = blockIdx.x * 32 + threadIdx.x;
    int y0 = blockIdx.y * 32;
#pragma unroll
    for (int i = threadIdx.y; i < 32; i += 8)
        tile[i][threadIdx.x] = in[(size_t)(y0 + i) * C + x];
    __syncthreads();
    int xo = blockIdx.y * 32 + threadIdx.x;
    int yo0 = blockIdx.x * 32;
#pragma unroll
    for (int i = threadIdx.y; i < 32; i += 8)
        out[(size_t)(yo0 + i) * R + xo] = tile[threadIdx.x][i];
}

// ---------------- launch ----------------------------------------------------
extern "C" void kernel_launch(void* const* d_in, const int* in_sizes, int n_in,
                              void* d_out, int out_size)
{
    const float* inq  = (const float*)d_in[0];
    const float* inkv = (const float*)d_in[1];
    const float* Wq   = (const float*)d_in[2];
    const float* Wk   = (const float*)d_in[3];
    const float* Wv   = (const float*)d_in[4];
    const float* Wo   = (const float*)d_in[5];
    float* out = (float*)d_out;

    __half *pQh, *pKh, *pVh;
    float *pC, *pWt;
    cudaGetSymbolAddress((void**)&pQh, g_Qh);
    cudaGetSymbolAddress((void**)&pKh, g_Kh);
    cudaGetSymbolAddress((void**)&pVh, g_Vh);
    cudaGetSymbolAddress((void**)&pC,  g_C);
    cudaGetSymbolAddress((void**)&pWt, g_Wt);
    float* pWtq = pWt;
    float* pWtk = pWt + (size_t)DD * DD;
    float* pWtv = pWt + (size_t)2 * DD * DD;
    float* pWto = pWt + (size_t)3 * DD * DD;

    cudaFuncSetAttribute(gemm_mma<0>, cudaFuncAttributeMaxDynamicSharedMemorySize, GEMM_SMEM);
    cudaFuncSetAttribute(gemm_mma<1>, cudaFuncAttributeMaxDynamicSharedMemorySize, GEMM_SMEM);
    cudaFuncSetAttribute(flash_attn, cudaFuncAttributeMaxDynamicSharedMemorySize, FA_SMEM);

    const float qscale = 1.0f / sqrtf((float)HD);
    dim3 tb(32, 8);

    // transpose weights to [N][K]
    transpose_k<<<dim3(DD / 32, DD / 32), tb>>>(Wq, pWtq, DD, DD);
    transpose_k<<<dim3(DD / 32, DD / 32), tb>>>(Wk, pWtk, DD, DD);
    transpose_k<<<dim3(DD / 32, DD / 32), tb>>>(Wv, pWtv, DD, DD);
    transpose_k<<<dim3(DD / 32, DD / 32), tb>>>(Wo, pWto, DD, DD);

    // projections -> fp16 Q/K/V (single-pass)
    dim3 pg(DD / 128, MTOK / 128);
    gemm_mma<1><<<pg, GT, GEMM_SMEM>>>(inq,  DD, pWtq, DD, pQh, DD, DD, qscale);
    gemm_mma<1><<<pg, GT, GEMM_SMEM>>>(inkv, DD, pWtk, DD, pKh, DD, DD, 1.0f);
    gemm_mma<1><<<pg, GT, GEMM_SMEM>>>(inkv, DD, pWtv, DD, pVh, DD, DD, 1.0f);

    // fused attention -> fp32 context
    dim3 fg(SS / 128, HH, BB);
    flash_attn<<<fg, 256, FA_SMEM>>>(pQh, pKh, pVh, pC);

    // output projection (single-pass, fp32 out)
    gemm_mma<0><<<pg, GT, GEMM_SMEM>>>(pC, DD, pWto, DD, out, DD, DD, 1.0f);
}

// round 9
// speedup vs baseline: 4.9912x; 1.1449x over previous
#include <cuda_runtime.h>
#include <cuda_fp16.h>
#include <stdint.h>
#include <math.h>

// Problem dims (fixed)
#define BB 8
#define SS 1024
#define DD 2048
#define HH 16
#define HD 128
#define MTOK (BB * SS)     // 8192
#define BHN (BB * HH)      // 128 batch-heads

// ---------------- scratch (device globals; allocation-free) ----------------
__device__ __half g_Xq [(size_t)MTOK * DD];    // fp16 inputs_q
__device__ __half g_Xkv[(size_t)MTOK * DD];    // fp16 inputs_kv
__device__ __half g_Qh[(size_t)MTOK * DD];     // fp16 Q (pre-scaled)
__device__ __half g_Kh[(size_t)MTOK * DD];
__device__ __half g_Vh[(size_t)MTOK * DD];
__device__ __half g_Ch[(size_t)MTOK * DD];     // fp16 attention context
__device__ __half g_Wh[4][(size_t)DD * DD];    // fp16 transposed weights (N-major)

// ---------------- common PTX helpers ---------------------------------------
__device__ __forceinline__ uint32_t smaddr(const void* p) {
    uint32_t a;
    asm("{ .reg .u64 t; cvta.to.shared.u64 t, %1; cvt.u32.u64 %0, t; }"
        : "=r"(a) : "l"(p));
    return a;
}
__device__ __forceinline__ void ldsm4(uint32_t addr, uint32_t* r) {
    asm volatile("ldmatrix.sync.aligned.m8n8.x4.shared.b16 {%0,%1,%2,%3}, [%4];"
                 : "=r"(r[0]), "=r"(r[1]), "=r"(r[2]), "=r"(r[3]) : "r"(addr));
}
__device__ __forceinline__ void ldsm4t(uint32_t addr, uint32_t* r) {
    asm volatile("ldmatrix.sync.aligned.m8n8.x4.trans.shared.b16 {%0,%1,%2,%3}, [%4];"
                 : "=r"(r[0]), "=r"(r[1]), "=r"(r[2]), "=r"(r[3]) : "r"(addr));
}
__device__ __forceinline__ void mma16816(float* c, const uint32_t* a, const uint32_t* b) {
    asm volatile(
        "mma.sync.aligned.m16n8k16.row.col.f32.f16.f16.f32 "
        "{%0,%1,%2,%3},{%4,%5,%6,%7},{%8,%9},{%0,%1,%2,%3};"
        : "+f"(c[0]), "+f"(c[1]), "+f"(c[2]), "+f"(c[3])
        : "r"(a[0]), "r"(a[1]), "r"(a[2]), "r"(a[3]), "r"(b[0]), "r"(b[1]));
}
__device__ __forceinline__ void cpasync16(uint32_t dst, const void* src) {
    asm volatile("cp.async.ca.shared.global [%0], [%1], 16;"
                 :: "r"(dst), "l"(src) : "memory");
}

// ---------------- mma.sync GEMM, fp16 operands, cp.async pipeline -----------
// D[M,N] = scale * A[M,K] @ B[N,K]^T ; A,B fp16 row-major.
// Block tile 128x128, BK=32, 256 threads (8 warps: 4m x 2n, 32x64 per warp).
// SMEM tile per operand: [row][64B], 4 chunks of 16B, swizzle c ^ (row & 3).
#define GT 256
#define BKC 32
#define TILE_BYTES 8192                 // 128 rows x 64 B
#define STAGE_BYTES (2 * TILE_BYTES)    // A + B
#define GEMM_SMEM (2 * STAGE_BYTES)     // 32 KB

template <int OUT16>
__global__ __launch_bounds__(GT) void gemm_h(
    const __half* __restrict__ A, long lda,
    const __half* __restrict__ B, long ldb,
    void* __restrict__ Cv, long ldc,
    int K, float scale)
{
    extern __shared__ char sm[];

    const int t = threadIdx.x;
    const int lane = t & 31;
    const int wid = t >> 5;
    const int wm = wid >> 1;
    const int wn = wid & 1;

    const __half* Ab = A + (size_t)(blockIdx.y * 128) * lda;
    const __half* Bb = B + (size_t)(blockIdx.x * 128) * ldb;

    const int sub = lane >> 3;
    const int rin = lane & 7;

    // cp.async mapping: thread handles rows rq, rq+64 at 16B chunk cq
    const int rq = t >> 2;            // 0..63
    const int cq = t & 3;             // 0..3

    float acc[2][8][4];
#pragma unroll
    for (int i = 0; i < 2; i++)
#pragma unroll
        for (int j = 0; j < 8; j++)
#pragma unroll
            for (int q = 0; q < 4; q++) acc[i][j][q] = 0.f;

    const int NC = K / BKC;
    const uint32_t smb = smaddr(sm);

    // prologue: issue chunk 0 into stage 0
    {
#pragma unroll
        for (int u = 0; u < 2; u++) {
            int row = rq + u * 64;
            uint32_t off = row * 64 + (((cq) ^ (row & 3)) << 4);
            cpasync16(smb + off, Ab + (size_t)row * lda + cq * 8);
            cpasync16(smb + TILE_BYTES + off, Bb + (size_t)row * ldb + cq * 8);
        }
        asm volatile("cp.async.commit_group;" ::: "memory");
    }

    for (int c = 0; c < NC; c++) {
        if (c + 1 < NC) {
            const int kt = (c + 1) * BKC;
            const uint32_t stb = smb + ((c + 1) & 1) * STAGE_BYTES;
#pragma unroll
            for (int u = 0; u < 2; u++) {
                int row = rq + u * 64;
                uint32_t off = row * 64 + (((cq) ^ (row & 3)) << 4);
                cpasync16(stb + off, Ab + (size_t)row * lda + kt + cq * 8);
                cpasync16(stb + TILE_BYTES + off, Bb + (size_t)row * ldb + kt + cq * 8);
            }
            asm volatile("cp.async.commit_group;" ::: "memory");
            asm volatile("cp.async.wait_group 1;" ::: "memory");
        } else {
            asm volatile("cp.async.wait_group 0;" ::: "memory");
        }
        __syncthreads();

        const uint32_t sA = smb + (c & 1) * STAGE_BYTES;
        const uint32_t sB = sA + TILE_BYTES;

#pragma unroll
        for (int ks = 0; ks < 2; ks++) {
            uint32_t Ah[2][4], Bh[4][4];
#pragma unroll
            for (int i = 0; i < 2; i++) {
                int arow = wm * 32 + i * 16 + rin + (sub & 1) * 8;
                int swz = arow & 3;
                int ch = 2 * ks + (sub >> 1);
                ldsm4(sA + arow * 64 + ((ch ^ swz) << 4), Ah[i]);
            }
#pragma unroll
            for (int p = 0; p < 4; p++) {
                int brow = wn * 64 + p * 16 + rin + (sub >> 1) * 8;
                int swz = brow & 3;
                int ch = 2 * ks + (sub & 1);
                ldsm4(sB + brow * 64 + ((ch ^ swz) << 4), Bh[p]);
            }
#pragma unroll
            for (int i = 0; i < 2; i++)
#pragma unroll
                for (int p = 0; p < 4; p++) {
                    mma16816(acc[i][2 * p + 0], Ah[i], &Bh[p][0]);
                    mma16816(acc[i][2 * p + 1], Ah[i], &Bh[p][2]);
                }
        }
        __syncthreads();
    }

    // epilogue
#pragma unroll
    for (int i = 0; i < 2; i++) {
        int r = blockIdx.y * 128 + wm * 32 + i * 16 + (lane >> 2);
#pragma unroll
        for (int j = 0; j < 8; j++) {
            int cc = blockIdx.x * 128 + wn * 64 + j * 8 + (lane & 3) * 2;
            if (OUT16) {
                __half* Co = (__half*)Cv;
                __half2 h0 = __floats2half2_rn(acc[i][j][0] * scale, acc[i][j][1] * scale);
                __half2 h1 = __floats2half2_rn(acc[i][j][2] * scale, acc[i][j][3] * scale);
                *(uint32_t*)&Co[(size_t)r * ldc + cc] = *(uint32_t*)&h0;
                *(uint32_t*)&Co[(size_t)(r + 8) * ldc + cc] = *(uint32_t*)&h1;
            } else {
                float* Co = (float*)Cv;
                float2 v0, v1;
                v0.x = acc[i][j][0] * scale; v0.y = acc[i][j][1] * scale;
                v1.x = acc[i][j][2] * scale; v1.y = acc[i][j][3] * scale;
                *(float2*)&Co[(size_t)r * ldc + cc] = v0;
                *(float2*)&Co[(size_t)(r + 8) * ldc + cc] = v1;
            }
        }
    }
}

// ---------------- fused flash attention (fp16 ctx out) ----------------------
#define FA_SMEM (32768 + 4 * 32768)

__device__ __forceinline__ uint32_t sw_off(int row, int c) {
    return (uint32_t)(row * 256 + ((c ^ (row & 7)) << 4));
}

__global__ __launch_bounds__(256, 1) void flash_attn(
    const __half* __restrict__ Q, const __half* __restrict__ K,
    const __half* __restrict__ V, __half* __restrict__ O)
{
    extern __shared__ char sm[];
    const uint32_t qs = smaddr(sm);
    const uint32_t ks0 = qs + 32768;
    const uint32_t vs0 = qs + 98304;

    const int t = threadIdx.x;
    const int lane = t & 31;
    const int wid = t >> 5;
    const int q0 = blockIdx.x * 128;
    const int hd0 = blockIdx.y * HD;
    const int tokB = blockIdx.z * SS;

    const __half* Kg = K + (size_t)tokB * DD + hd0;
    const __half* Vg = V + (size_t)tokB * DD + hd0;

    const int lr = t >> 4;
    const int lc = t & 15;
    {
#pragma unroll
        for (int j = 0; j < 8; j++) {
            int row = lr + j * 16;
            cpasync16(ks0 + sw_off(row, lc), Kg + (size_t)row * DD + lc * 8);
        }
#pragma unroll
        for (int j = 0; j < 8; j++) {
            int row = lr + j * 16;
            cpasync16(vs0 + sw_off(row, lc), Vg + (size_t)row * DD + lc * 8);
        }
        asm volatile("cp.async.commit_group;" ::: "memory");
    }

    {
        const __half* qg = Q + (size_t)(tokB + q0) * DD + hd0;
#pragma unroll
        for (int j = 0; j < 8; j++) {
            int row = lr + j * 16;
            uint4 v = *(const uint4*)(qg + (size_t)row * DD + lc * 8);
            *(uint4*)(sm + sw_off(row, lc)) = v;
        }
    }
    __syncthreads();

    uint32_t Qfr[8][4];
    {
        const int rloc = wid * 16 + (lane & 15);
#pragma unroll
        for (int kk = 0; kk < 8; kk++) {
            int c = 2 * kk + (lane >> 4);
            ldsm4(qs + sw_off(rloc, c), Qfr[kk]);
        }
    }

    float accO[16][4];
#pragma unroll
    for (int nt = 0; nt < 16; nt++)
#pragma unroll
        for (int q = 0; q < 4; q++) accO[nt][q] = 0.f;
    float m0 = -1e30f, m1 = -1e30f, l0 = 0.f, l1 = 0.f;

    for (int it = 0; it < SS / 128; it++) {
        const uint32_t ksb = ks0 + (it & 1) * 32768;
        const uint32_t vsb = vs0 + (it & 1) * 32768;

        if (it + 1 < SS / 128) {
            const uint32_t kn = ks0 + ((it + 1) & 1) * 32768;
            const uint32_t vn = vs0 + ((it + 1) & 1) * 32768;
            const __half* kg = Kg + (size_t)(it + 1) * 128 * DD;
            const __half* vg = Vg + (size_t)(it + 1) * 128 * DD;
#pragma unroll
            for (int j = 0; j < 8; j++) {
                int row = lr + j * 16;
                cpasync16(kn + sw_off(row, lc), kg + (size_t)row * DD + lc * 8);
            }
#pragma unroll
            for (int j = 0; j < 8; j++) {
                int row = lr + j * 16;
                cpasync16(vn + sw_off(row, lc), vg + (size_t)row * DD + lc * 8);
            }
            asm volatile("cp.async.commit_group;" ::: "memory");
            asm volatile("cp.async.wait_group 1;" ::: "memory");
        } else {
            asm volatile("cp.async.wait_group 0;" ::: "memory");
        }
        __syncthreads();

        float accS[16][4];
#pragma unroll
        for (int nt = 0; nt < 16; nt++)
#pragma unroll
            for (int q = 0; q < 4; q++) accS[nt][q] = 0.f;

#pragma unroll
        for (int np = 0; np < 8; np++) {
            const int krow = np * 16 + (lane & 7) + ((lane >> 4) << 3);
#pragma unroll
            for (int kk = 0; kk < 8; kk++) {
                uint32_t Bf[4];
                int c = 2 * kk + ((lane >> 3) & 1);
                ldsm4(ksb + sw_off(krow, c), Bf);
                mma16816(accS[2 * np + 0], Qfr[kk], &Bf[0]);
                mma16816(accS[2 * np + 1], Qfr[kk], &Bf[2]);
            }
        }

        float mx0 = -1e30f, mx1 = -1e30f;
#pragma unroll
        for (int nt = 0; nt < 16; nt++) {
            mx0 = fmaxf(mx0, fmaxf(accS[nt][0], accS[nt][1]));
            mx1 = fmaxf(mx1, fmaxf(accS[nt][2], accS[nt][3]));
        }
        mx0 = fmaxf(mx0, __shfl_xor_sync(~0u, mx0, 1));
        mx0 = fmaxf(mx0, __shfl_xor_sync(~0u, mx0, 2));
        mx1 = fmaxf(mx1, __shfl_xor_sync(~0u, mx1, 1));
        mx1 = fmaxf(mx1, __shfl_xor_sync(~0u, mx1, 2));

        float mn0 = fmaxf(m0, mx0), mn1 = fmaxf(m1, mx1);
        float a0 = __expf(m0 - mn0), a1 = __expf(m1 - mn1);
        m0 = mn0; m1 = mn1;

        float s0 = 0.f, s1 = 0.f;
#pragma unroll
        for (int nt = 0; nt < 16; nt++) {
            accS[nt][0] = __expf(accS[nt][0] - m0); s0 += accS[nt][0];
            accS[nt][1] = __expf(accS[nt][1] - m0); s0 += accS[nt][1];
            accS[nt][2] = __expf(accS[nt][2] - m1); s1 += accS[nt][2];
            accS[nt][3] = __expf(accS[nt][3] - m1); s1 += accS[nt][3];
        }
        s0 += __shfl_xor_sync(~0u, s0, 1); s0 += __shfl_xor_sync(~0u, s0, 2);
        s1 += __shfl_xor_sync(~0u, s1, 1); s1 += __shfl_xor_sync(~0u, s1, 2);
        l0 = l0 * a0 + s0;
        l1 = l1 * a1 + s1;

#pragma unroll
        for (int nt = 0; nt < 16; nt++) {
            accO[nt][0] *= a0; accO[nt][1] *= a0;
            accO[nt][2] *= a1; accO[nt][3] *= a1;
        }

#pragma unroll
        for (int kk = 0; kk < 8; kk++) {
            uint32_t Pf[4];
            __half2 p0 = __floats2half2_rn(accS[2 * kk][0], accS[2 * kk][1]);
            __half2 p1 = __floats2half2_rn(accS[2 * kk][2], accS[2 * kk][3]);
            __half2 p2 = __floats2half2_rn(accS[2 * kk + 1][0], accS[2 * kk + 1][1]);
            __half2 p3 = __floats2half2_rn(accS[2 * kk + 1][2], accS[2 * kk + 1][3]);
            Pf[0] = *(uint32_t*)&p0; Pf[1] = *(uint32_t*)&p1;
            Pf[2] = *(uint32_t*)&p2; Pf[3] = *(uint32_t*)&p3;

            const int vrow = kk * 16 + (lane & 15);
#pragma unroll
            for (int nd = 0; nd < 8; nd++) {
                uint32_t Bf[4];
                int c = 2 * nd + (lane >> 4);
                ldsm4t(vsb + sw_off(vrow, c), Bf);
                mma16816(accO[2 * nd + 0], Pf, &Bf[0]);
                mma16816(accO[2 * nd + 1], Pf, &Bf[2]);
            }
        }
        __syncthreads();
    }

    // write fp16 context (normalized)
    const float i0 = 1.f / l0, i1 = 1.f / l1;
    const int r0 = tokB + q0 + wid * 16 + (lane >> 2);
#pragma unroll
    for (int nt = 0; nt < 16; nt++) {
        int d = hd0 + nt * 8 + (lane & 3) * 2;
        __half2 v0 = __floats2half2_rn(accO[nt][0] * i0, accO[nt][1] * i0);
        __half2 v1 = __floats2half2_rn(accO[nt][2] * i1, accO[nt][3] * i1);
        *(uint32_t*)&O[(size_t)r0 * DD + d] = *(uint32_t*)&v0;
        *(uint32_t*)&O[(size_t)(r0 + 8) * DD + d] = *(uint32_t*)&v1;
    }
}

// ---------------- fp32 -> fp16 transpose (weights) --------------------------
__global__ __launch_bounds__(256) void transpose_h(
    const float* __restrict__ in, __half* __restrict__ out, int R, int C)
{
    __shared__ float tile[32][33];
    int x = blockIdx.x * 32 + threadIdx.x;
    int y0 = blockIdx.y * 32;
#pragma unroll
    for (int i = threadIdx.y; i < 32; i += 8)
        tile[i][threadIdx.x] = in[(size_t)(y0 + i) * C + x];
    __syncthreads();
    int xo = blockIdx.y * 32 + threadIdx.x;
    int yo0 = blockIdx.x * 32;
#pragma unroll
    for (int i = threadIdx.y; i < 32; i += 8)
        out[(size_t)(yo0 + i) * R + xo] = __float2half_rn(tile[threadIdx.x][i]);
}

// ---------------- fp32 -> fp16 elementwise ----------------------------------
__global__ __launch_bounds__(256) void cvt_h(
    const float* __restrict__ in, __half* __restrict__ out)
{
    size_t i = ((size_t)blockIdx.x * 256 + threadIdx.x) * 4;
    float4 v = *(const float4*)(in + i);
    __half2 h0 = __floats2half2_rn(v.x, v.y);
    __half2 h1 = __floats2half2_rn(v.z, v.w);
    *(uint2*)(out + i) = make_uint2(*(uint32_t*)&h0, *(uint32_t*)&h1);
}

// ---------------- launch ----------------------------------------------------
extern "C" void kernel_launch(void* const* d_in, const int* in_sizes, int n_in,
                              void* d_out, int out_size)
{
    const float* inq  = (const float*)d_in[0];
    const float* inkv = (const float*)d_in[1];
    const float* Wq   = (const float*)d_in[2];
    const float* Wk   = (const float*)d_in[3];
    const float* Wv   = (const float*)d_in[4];
    const float* Wo   = (const float*)d_in[5];
    float* out = (float*)d_out;

    __half *pXq, *pXkv, *pQh, *pKh, *pVh, *pCh, *pWh;
    cudaGetSymbolAddress((void**)&pXq,  g_Xq);
    cudaGetSymbolAddress((void**)&pXkv, g_Xkv);
    cudaGetSymbolAddress((void**)&pQh,  g_Qh);
    cudaGetSymbolAddress((void**)&pKh,  g_Kh);
    cudaGetSymbolAddress((void**)&pVh,  g_Vh);
    cudaGetSymbolAddress((void**)&pCh,  g_Ch);
    cudaGetSymbolAddress((void**)&pWh,  g_Wh);
    __half* pWhq = pWh;
    __half* pWhk = pWh + (size_t)DD * DD;
    __half* pWhv = pWh + (size_t)2 * DD * DD;
    __half* pWho = pWh + (size_t)3 * DD * DD;

    cudaFuncSetAttribute(gemm_h<0>, cudaFuncAttributeMaxDynamicSharedMemorySize, GEMM_SMEM);
    cudaFuncSetAttribute(gemm_h<1>, cudaFuncAttributeMaxDynamicSharedMemorySize, GEMM_SMEM);
    cudaFuncSetAttribute(flash_attn, cudaFuncAttributeMaxDynamicSharedMemorySize, FA_SMEM);

    const float qscale = 1.0f / sqrtf((float)HD);
    dim3 tb(32, 8);

    // inputs -> fp16
    const unsigned nv = (unsigned)((size_t)MTOK * DD / 4 / 256);
    cvt_h<<<nv, 256>>>(inq,  pXq);
    cvt_h<<<nv, 256>>>(inkv, pXkv);

    // weights -> fp16, transposed to [N][K]
    transpose_h<<<dim3(DD / 32, DD / 32), tb>>>(Wq, pWhq, DD, DD);
    transpose_h<<<dim3(DD / 32, DD / 32), tb>>>(Wk, pWhk, DD, DD);
    transpose_h<<<dim3(DD / 32, DD / 32), tb>>>(Wv, pWhv, DD, DD);
    transpose_h<<<dim3(DD / 32, DD / 32), tb>>>(Wo, pWho, DD, DD);

    // projections -> fp16 Q/K/V
    dim3 pg(DD / 128, MTOK / 128);
    gemm_h<1><<<pg, GT, GEMM_SMEM>>>(pXq,  DD, pWhq, DD, pQh, DD, DD, qscale);
    gemm_h<1><<<pg, GT, GEMM_SMEM>>>(pXkv, DD, pWhk, DD, pKh, DD, DD, 1.0f);
    gemm_h<1><<<pg, GT, GEMM_SMEM>>>(pXkv, DD, pWhv, DD, pVh, DD, DD, 1.0f);

    // fused attention -> fp16 context
    dim3 fg(SS / 128, HH, BB);
    flash_attn<<<fg, 256, FA_SMEM>>>(pQh, pKh, pVh, pCh);

    // output projection (fp32 out)
    gemm_h<0><<<pg, GT, GEMM_SMEM>>>(pCh, DD, pWho, DD, out, DD, DD, 1.0f);
}